// round 3
// baseline (speedup 1.0000x reference)
#include <cuda_runtime.h>
#include <math.h>
#include <stdint.h>

// Problem constants
#define BB 64
#define NN 128
#define JJ 512
#define DD 1024
#define HH 4096
#define MM (BB * NN)          // 8192 rows
#define SCALE 0.03125f        // 1024^-0.5
#define EPS 1e-8f
#define LN_EPS 1e-5f

// ---------------------------------------------------------------------------
// Scratch (device globals; no allocations allowed)
// ---------------------------------------------------------------------------
__device__ float g_txn [JJ * DD];
__device__ float g_k   [JJ * DD];
__device__ float g_v   [JJ * DD];
__device__ float g_vT  [DD * JJ];
__device__ float g_slots[MM * DD];
__device__ float g_ln  [MM * DD];
__device__ float g_q   [MM * DD];
__device__ float g_attn[MM * JJ];
__device__ float g_upd [MM * DD];
__device__ float g_gi  [MM * 3 * DD];
__device__ float g_gh  [MM * 3 * DD];
__device__ float g_hid [MM * HH];

// ---------------------------------------------------------------------------
// Helpers
// ---------------------------------------------------------------------------
__device__ __forceinline__ float warp_sum(float v) {
    #pragma unroll
    for (int o = 16; o; o >>= 1) v += __shfl_xor_sync(0xFFFFFFFFu, v, o);
    return v;
}

// ---------------------------------------------------------------------------
// LayerNorm: one block per row, D = 1024, 256 threads (1 float4 / thread)
// ---------------------------------------------------------------------------
__global__ void ln_kernel(const float* __restrict__ x, float* __restrict__ y,
                          const float* __restrict__ g, const float* __restrict__ b) {
    const int row = blockIdx.x;
    const int t = threadIdx.x;
    const float4* xr = (const float4*)(x + (size_t)row * DD);
    float4 v = xr[t];
    float s = v.x + v.y + v.z + v.w;
    float q = v.x * v.x + v.y * v.y + v.z * v.z + v.w * v.w;
    s = warp_sum(s);
    q = warp_sum(q);
    __shared__ float s1[8], s2[8];
    if ((t & 31) == 0) { s1[t >> 5] = s; s2[t >> 5] = q; }
    __syncthreads();
    float S = 0.f, Q = 0.f;
    #pragma unroll
    for (int w = 0; w < 8; w++) { S += s1[w]; Q += s2[w]; }
    const float mean = S * (1.f / DD);
    const float var  = Q * (1.f / DD) - mean * mean;
    const float inv  = rsqrtf(var + LN_EPS);
    float4 gv = ((const float4*)g)[t];
    float4 bv = ((const float4*)b)[t];
    float4 o;
    o.x = (v.x - mean) * inv * gv.x + bv.x;
    o.y = (v.y - mean) * inv * gv.y + bv.y;
    o.z = (v.z - mean) * inv * gv.z + bv.z;
    o.w = (v.w - mean) * inv * gv.w + bv.w;
    ((float4*)(y + (size_t)row * DD))[t] = o;
}

// ---------------------------------------------------------------------------
// NT GEMM: C[M,N] = alpha * A[M,K] @ B[N,K]^T (+bias) (relu) (+resid)
// BM=BN=128, BK=16, 256 threads, 8x8 per thread. M%128==0, N%128==0, K%16==0.
// ---------------------------------------------------------------------------
#define BM 128
#define BN 128
#define BK 16

__global__ __launch_bounds__(256, 2)
void gemm_nt_kernel(const float* __restrict__ A, const float* __restrict__ Bw,
                    float* __restrict__ C, int M, int N, int K,
                    const float* __restrict__ bias, const float* __restrict__ resid,
                    float alpha, int relu) {
    __shared__ __align__(16) float As[BK][BM];
    __shared__ __align__(16) float Bs[BK][BN];

    const int tid = threadIdx.x;
    const int bm = blockIdx.y * BM;
    const int bn = blockIdx.x * BN;

    const int lrow = tid >> 2;          // 0..63
    const int lcol = (tid & 3) << 2;    // 0,4,8,12

    const float* Ap = A  + (size_t)(bm + lrow) * K + lcol;
    const float* Bp = Bw + (size_t)(bn + lrow) * K + lcol;

    const int rm = (tid >> 4) << 3;     // 0..120
    const int rn = (tid & 15) << 3;     // 0..120

    float acc[8][8];
    #pragma unroll
    for (int i = 0; i < 8; i++)
        #pragma unroll
        for (int j = 0; j < 8; j++) acc[i][j] = 0.f;

    for (int k0 = 0; k0 < K; k0 += BK) {
        float4 a0 = *(const float4*)(Ap + k0);
        float4 a1 = *(const float4*)(Ap + (size_t)64 * K + k0);
        float4 b0 = *(const float4*)(Bp + k0);
        float4 b1 = *(const float4*)(Bp + (size_t)64 * K + k0);

        As[lcol + 0][lrow]      = a0.x;
        As[lcol + 1][lrow]      = a0.y;
        As[lcol + 2][lrow]      = a0.z;
        As[lcol + 3][lrow]      = a0.w;
        As[lcol + 0][lrow + 64] = a1.x;
        As[lcol + 1][lrow + 64] = a1.y;
        As[lcol + 2][lrow + 64] = a1.z;
        As[lcol + 3][lrow + 64] = a1.w;

        Bs[lcol + 0][lrow]      = b0.x;
        Bs[lcol + 1][lrow]      = b0.y;
        Bs[lcol + 2][lrow]      = b0.z;
        Bs[lcol + 3][lrow]      = b0.w;
        Bs[lcol + 0][lrow + 64] = b1.x;
        Bs[lcol + 1][lrow + 64] = b1.y;
        Bs[lcol + 2][lrow + 64] = b1.z;
        Bs[lcol + 3][lrow + 64] = b1.w;

        __syncthreads();

        #pragma unroll
        for (int kk = 0; kk < BK; kk++) {
            float a[8], b[8];
            *(float4*)(&a[0]) = *(const float4*)(&As[kk][rm]);
            *(float4*)(&a[4]) = *(const float4*)(&As[kk][rm + 4]);
            *(float4*)(&b[0]) = *(const float4*)(&Bs[kk][rn]);
            *(float4*)(&b[4]) = *(const float4*)(&Bs[kk][rn + 4]);
            #pragma unroll
            for (int i = 0; i < 8; i++)
                #pragma unroll
                for (int j = 0; j < 8; j++)
                    acc[i][j] = fmaf(a[i], b[j], acc[i][j]);
        }
        __syncthreads();
    }

    #pragma unroll
    for (int i = 0; i < 8; i++) {
        const int row = bm + rm + i;
        float* Crow = C + (size_t)row * N + bn + rn;
        const float* Rrow = resid ? (resid + (size_t)row * N + bn + rn) : (const float*)0;
        #pragma unroll
        for (int j = 0; j < 8; j++) {
            float vv = acc[i][j] * alpha;
            if (bias) vv += bias[bn + rn + j];
            if (relu) vv = fmaxf(vv, 0.f);
            if (Rrow) vv += Rrow[j];
            Crow[j] = vv;
        }
    }
}

// ---------------------------------------------------------------------------
// Transpose (rows x cols) -> (cols x rows), 32x32 tiles
// ---------------------------------------------------------------------------
__global__ void transpose_kernel(const float* __restrict__ in, float* __restrict__ out,
                                 int R, int C) {
    __shared__ float tile[32][33];
    const int c0 = blockIdx.x * 32;
    const int r0 = blockIdx.y * 32;
    for (int dy = threadIdx.y; dy < 32; dy += 8)
        tile[dy][threadIdx.x] = in[(size_t)(r0 + dy) * C + c0 + threadIdx.x];
    __syncthreads();
    for (int dy = threadIdx.y; dy < 32; dy += 8)
        out[(size_t)(c0 + dy) * R + r0 + threadIdx.x] = tile[threadIdx.x][dy];
}

// ---------------------------------------------------------------------------
// Softmax over the slots axis (i), per (b, j) column. attn laid out [B*N, J].
// Block: 128 threads handles 32 consecutive j for one b (coalesced).
// Writes softmax + EPS in place.
// ---------------------------------------------------------------------------
__global__ void colsoftmax_kernel(float* __restrict__ attn) {
    const int b = blockIdx.y;
    const int t = threadIdx.x;          // 0..127
    const int lane = t & 31;
    const int r = t >> 5;               // 0..3
    const int j = blockIdx.x * 32 + lane;
    float* base = attn + (size_t)b * NN * JJ;

    float m = -3.0e38f, s = 0.f;
    for (int i = r; i < NN; i += 4) {
        float x = base[(size_t)i * JJ + j];
        float nm = fmaxf(m, x);
        s = s * expf(m - nm) + expf(x - nm);
        m = nm;
    }
    __shared__ float sm[4][32], ss[4][32], gm[32], gs[32];
    sm[r][lane] = m;
    ss[r][lane] = s;
    __syncthreads();
    if (r == 0) {
        float M = sm[0][lane];
        #pragma unroll
        for (int p = 1; p < 4; p++) M = fmaxf(M, sm[p][lane]);
        float S = 0.f;
        #pragma unroll
        for (int p = 0; p < 4; p++) S += ss[p][lane] * expf(sm[p][lane] - M);
        gm[lane] = M;
        gs[lane] = 1.f / S;
    }
    __syncthreads();
    const float M = gm[lane], invS = gs[lane];
    for (int i = r; i < NN; i += 4) {
        size_t o = (size_t)i * JJ + j;
        base[o] = expf(base[o] - M) * invS + EPS;
    }
}

// ---------------------------------------------------------------------------
// Row renormalization over j: attn[row, :] /= sum_j attn[row, j]
// ---------------------------------------------------------------------------
__global__ void rownorm_kernel(float* __restrict__ attn) {
    const int row = blockIdx.x;
    float* a = attn + (size_t)row * JJ;
    float s = 0.f;
    for (int i = threadIdx.x; i < JJ; i += 128) s += a[i];
    s = warp_sum(s);
    __shared__ float ws[4];
    if ((threadIdx.x & 31) == 0) ws[threadIdx.x >> 5] = s;
    __syncthreads();
    const float inv = 1.f / (ws[0] + ws[1] + ws[2] + ws[3]);
    for (int i = threadIdx.x; i < JJ; i += 128) a[i] *= inv;
}

// ---------------------------------------------------------------------------
// GRU cell elementwise (torch gate order r, z, n). In-place slots update.
// ---------------------------------------------------------------------------
__global__ void gru_kernel(const float* __restrict__ gi, const float* __restrict__ gh,
                           float* __restrict__ slots) {
    const int idx = blockIdx.x * blockDim.x + threadIdx.x;  // 0 .. MM*DD-1
    const int m = idx >> 10;
    const int d = idx & 1023;
    const size_t o = (size_t)m * (3 * DD) + d;
    const float r = 1.f / (1.f + expf(-(gi[o] + gh[o])));
    const float z = 1.f / (1.f + expf(-(gi[o + DD] + gh[o + DD])));
    const float n = tanhf(gi[o + 2 * DD] + r * gh[o + 2 * DD]);
    const float h = slots[idx];
    slots[idx] = (1.f - z) * n + z * h;
}

// ---------------------------------------------------------------------------
// Launch
// ---------------------------------------------------------------------------
static inline void gemm(const float* A, const float* B, float* C, int M, int N, int K,
                        const float* bias, const float* resid, float alpha, int relu) {
    dim3 grid(N / BN, M / BM);
    gemm_nt_kernel<<<grid, 256>>>(A, B, C, M, N, K, bias, resid, alpha, relu);
}

extern "C" void kernel_launch(void* const* d_in, const int* in_sizes, int n_in,
                              void* d_out, int out_size) {
    const float* inputs = (const float*)d_in[0];
    const float* texts  = (const float*)d_in[1];
    const float* Wq   = (const float*)d_in[2];  const float* bq   = (const float*)d_in[3];
    const float* Wk   = (const float*)d_in[4];  const float* bk   = (const float*)d_in[5];
    const float* Wv   = (const float*)d_in[6];  const float* bv   = (const float*)d_in[7];
    const float* W_ih = (const float*)d_in[8];  const float* b_ih = (const float*)d_in[9];
    const float* W_hh = (const float*)d_in[10]; const float* b_hh = (const float*)d_in[11];
    const float* W1   = (const float*)d_in[12]; const float* b1   = (const float*)d_in[13];
    const float* W2   = (const float*)d_in[14]; const float* b2   = (const float*)d_in[15];
    const float* gin  = (const float*)d_in[16]; const float* bein = (const float*)d_in[17];
    const float* gsl  = (const float*)d_in[18]; const float* besl = (const float*)d_in[19];
    const float* gff  = (const float*)d_in[20]; const float* beff = (const float*)d_in[21];

    float *txn, *k, *v, *vT, *slots, *lnb, *q, *attn, *upd, *gi, *gh, *hid;
    cudaGetSymbolAddress((void**)&txn,  g_txn);
    cudaGetSymbolAddress((void**)&k,    g_k);
    cudaGetSymbolAddress((void**)&v,    g_v);
    cudaGetSymbolAddress((void**)&vT,   g_vT);
    cudaGetSymbolAddress((void**)&slots,g_slots);
    cudaGetSymbolAddress((void**)&lnb,  g_ln);
    cudaGetSymbolAddress((void**)&q,    g_q);
    cudaGetSymbolAddress((void**)&attn, g_attn);
    cudaGetSymbolAddress((void**)&upd,  g_upd);
    cudaGetSymbolAddress((void**)&gi,   g_gi);
    cudaGetSymbolAddress((void**)&gh,   g_gh);
    cudaGetSymbolAddress((void**)&hid,  g_hid);

    // slots = inputs
    cudaMemcpyAsync(slots, inputs, (size_t)MM * DD * sizeof(float),
                    cudaMemcpyDeviceToDevice);

    // texts_n = LN(texts); k = texts_n @ Wk^T + bk; v likewise; vT = v^T
    ln_kernel<<<JJ, 256>>>(texts, txn, gin, bein);
    gemm(txn, Wk, k, JJ, DD, DD, bk, 0, 1.f, 0);
    gemm(txn, Wv, v, JJ, DD, DD, bv, 0, 1.f, 0);
    transpose_kernel<<<dim3(DD / 32, JJ / 32), dim3(32, 8)>>>(v, vT, JJ, DD);

    for (int it = 0; it < 3; it++) {
        // q = LN(slots) @ Wq^T + bq
        ln_kernel<<<MM, 256>>>(slots, lnb, gsl, besl);
        gemm(lnb, Wq, q, MM, DD, DD, bq, 0, 1.f, 0);

        // dots = q @ k^T * SCALE   -> attn buffer [MM, JJ]
        gemm(q, k, attn, MM, JJ, DD, 0, 0, SCALE, 0);

        // softmax over slots axis (+EPS), then renormalize over j
        colsoftmax_kernel<<<dim3(JJ / 32, BB), 128>>>(attn);
        rownorm_kernel<<<MM, 128>>>(attn);

        // updates = attn @ v  (via vT, NT form)
        gemm(attn, vT, upd, MM, DD, JJ, 0, 0, 1.f, 0);

        // GRU gates
        gemm(upd,   W_ih, gi, MM, 3 * DD, DD, b_ih, 0, 1.f, 0);
        gemm(slots, W_hh, gh, MM, 3 * DD, DD, b_hh, 0, 1.f, 0);
        gru_kernel<<<(MM * DD) / 256, 256>>>(gi, gh, slots);

        // FF: slots += relu(LN(slots) @ W1^T + b1) @ W2^T + b2
        ln_kernel<<<MM, 256>>>(slots, lnb, gff, beff);
        gemm(lnb, W1, hid, MM, HH, DD, b1, 0, 1.f, 1);
        float* outp = (it == 2) ? (float*)d_out : slots;
        gemm(hid, W2, outp, MM, DD, HH, b2, slots, 1.f, 0);
    }
}

// round 5
// speedup vs baseline: 3.3188x; 3.3188x over previous
#include <cuda_runtime.h>
#include <math.h>
#include <stdint.h>

// Problem constants
#define BB 64
#define NN 128
#define JJ 512
#define DD 1024
#define HH 4096
#define MM (BB * NN)          // 8192 rows
#define SCALE 0.03125f        // 1024^-0.5
#define EPS 1e-8f
#define LN_EPS 1e-5f

// ---------------------------------------------------------------------------
// Scratch (device globals; no allocations allowed)
// ---------------------------------------------------------------------------
__device__ float g_txn [JJ * DD];
__device__ float g_k   [JJ * DD];
__device__ float g_v   [JJ * DD];
__device__ float g_vT  [DD * JJ];
__device__ float g_slots[MM * DD];
__device__ float g_ln  [MM * DD];
__device__ float g_q   [MM * DD];
__device__ float g_attn[MM * JJ];
__device__ float g_upd [MM * DD];
__device__ float g_gi  [MM * 3 * DD];
__device__ float g_gh  [MM * 3 * DD];
__device__ float g_hid [MM * HH];

// ---------------------------------------------------------------------------
// Helpers
// ---------------------------------------------------------------------------
__device__ __forceinline__ float warp_sum(float v) {
    #pragma unroll
    for (int o = 16; o; o >>= 1) v += __shfl_xor_sync(0xFFFFFFFFu, v, o);
    return v;
}

__device__ __forceinline__ uint32_t f2tf32(float f) {
    uint32_t u;
    asm("cvt.rna.tf32.f32 %0, %1;" : "=r"(u) : "f"(f));
    return u;
}

// m16n8k8 tf32 MMA (sm_80+ baseline instruction; legal on compute_103)
__device__ __forceinline__ void mma_tf32(float* c,
                                         uint32_t a0, uint32_t a1, uint32_t a2, uint32_t a3,
                                         uint32_t b0, uint32_t b1) {
    asm volatile(
        "mma.sync.aligned.m16n8k8.row.col.f32.tf32.tf32.f32 "
        "{%0,%1,%2,%3}, {%4,%5,%6,%7}, {%8,%9}, {%0,%1,%2,%3};"
        : "+f"(c[0]), "+f"(c[1]), "+f"(c[2]), "+f"(c[3])
        : "r"(a0), "r"(a1), "r"(a2), "r"(a3), "r"(b0), "r"(b1));
}

// ---------------------------------------------------------------------------
// LayerNorm: one block per row, D = 1024, 256 threads (1 float4 / thread)
// ---------------------------------------------------------------------------
__global__ void ln_kernel(const float* __restrict__ x, float* __restrict__ y,
                          const float* __restrict__ g, const float* __restrict__ b) {
    const int row = blockIdx.x;
    const int t = threadIdx.x;
    const float4* xr = (const float4*)(x + (size_t)row * DD);
    float4 v = xr[t];
    float s = v.x + v.y + v.z + v.w;
    float q = v.x * v.x + v.y * v.y + v.z * v.z + v.w * v.w;
    s = warp_sum(s);
    q = warp_sum(q);
    __shared__ float s1[8], s2[8];
    if ((t & 31) == 0) { s1[t >> 5] = s; s2[t >> 5] = q; }
    __syncthreads();
    float S = 0.f, Q = 0.f;
    #pragma unroll
    for (int w = 0; w < 8; w++) { S += s1[w]; Q += s2[w]; }
    const float mean = S * (1.f / DD);
    const float var  = Q * (1.f / DD) - mean * mean;
    const float inv  = rsqrtf(var + LN_EPS);
    float4 gv = ((const float4*)g)[t];
    float4 bv = ((const float4*)b)[t];
    float4 o;
    o.x = (v.x - mean) * inv * gv.x + bv.x;
    o.y = (v.y - mean) * inv * gv.y + bv.y;
    o.z = (v.z - mean) * inv * gv.z + bv.z;
    o.w = (v.w - mean) * inv * gv.w + bv.w;
    ((float4*)(y + (size_t)row * DD))[t] = o;
}

// ---------------------------------------------------------------------------
// Tensor-core TF32 NT GEMM: C[M,N] = alpha*A[M,K]@B[N,K]^T (+bias)(relu)(+resid)
// CTA tile 128x128, BK=32, 256 threads (8 warps, warp tile 64x32).
// mma.sync.m16n8k8 tf32, fp32 accumulate. M,N%128==0, K%32==0.
// ---------------------------------------------------------------------------
#define BK 32
#define LDP 36    // SMEM row stride in floats (32 + 4 pad)

__global__ __launch_bounds__(256, 2)
void gemm_tc_kernel(const float* __restrict__ A, const float* __restrict__ Bw,
                    float* __restrict__ C, int M, int N, int K,
                    const float* __restrict__ bias, const float* __restrict__ resid,
                    float alpha, int relu) {
    __shared__ __align__(16) float As[128][LDP];
    __shared__ __align__(16) float Bs[128][LDP];

    const int tid  = threadIdx.x;
    const int warp = tid >> 5;
    const int lane = tid & 31;
    const int gid  = lane >> 2;          // 0..7
    const int tig  = lane & 3;           // 0..3
    const int wm = (warp >> 2) * 64;     // warp m-offset (0 or 64)
    const int wn = (warp & 3) * 32;      // warp n-offset (0,32,64,96)

    const int bm = blockIdx.y * 128;
    const int bn = blockIdx.x * 128;

    // Staging map: idx = tid + 256p -> row r = idx>>3, float4 slot f4 = idx&7
    const int sr0 = tid >> 3;            // base row for p=0 (rows advance by 32/p)
    const int sf4 = tid & 7;

    float acc[4][4][4];
    #pragma unroll
    for (int mf = 0; mf < 4; mf++)
        #pragma unroll
        for (int nf = 0; nf < 4; nf++)
            #pragma unroll
            for (int u = 0; u < 4; u++) acc[mf][nf][u] = 0.f;

    const int nch = K >> 5;

    float4 Ar[4], Br[4];
    // prefetch chunk 0
    #pragma unroll
    for (int p = 0; p < 4; p++) {
        const int r = sr0 + p * 32;
        Ar[p] = *(const float4*)(A  + (size_t)(bm + r) * K + sf4 * 4);
        Br[p] = *(const float4*)(Bw + (size_t)(bn + r) * K + sf4 * 4);
    }

    for (int c = 0; c < nch; c++) {
        // store prefetched chunk (fp32 -> tf32 RN) into SMEM
        #pragma unroll
        for (int p = 0; p < 4; p++) {
            const int r = sr0 + p * 32;
            uint4 at = { f2tf32(Ar[p].x), f2tf32(Ar[p].y), f2tf32(Ar[p].z), f2tf32(Ar[p].w) };
            uint4 bt = { f2tf32(Br[p].x), f2tf32(Br[p].y), f2tf32(Br[p].z), f2tf32(Br[p].w) };
            *(uint4*)(&As[r][sf4 * 4]) = at;
            *(uint4*)(&Bs[r][sf4 * 4]) = bt;
        }
        __syncthreads();

        // issue next chunk's global loads (in flight under the MMAs)
        if (c + 1 < nch) {
            const int k0 = (c + 1) << 5;
            #pragma unroll
            for (int p = 0; p < 4; p++) {
                const int r = sr0 + p * 32;
                Ar[p] = *(const float4*)(A  + (size_t)(bm + r) * K + k0 + sf4 * 4);
                Br[p] = *(const float4*)(Bw + (size_t)(bn + r) * K + k0 + sf4 * 4);
            }
        }

        // compute: 4 k-steps of m16n8k8
        #pragma unroll
        for (int ks = 0; ks < 4; ks++) {
            const int kk = ks * 8;
            uint32_t b[4][2];
            #pragma unroll
            for (int nf = 0; nf < 4; nf++) {
                const int n = wn + nf * 8 + gid;
                b[nf][0] = __float_as_uint(Bs[n][kk + tig]);
                b[nf][1] = __float_as_uint(Bs[n][kk + tig + 4]);
            }
            #pragma unroll
            for (int mf = 0; mf < 4; mf++) {
                const int m = wm + mf * 16 + gid;
                uint32_t a0 = __float_as_uint(As[m][kk + tig]);
                uint32_t a1 = __float_as_uint(As[m + 8][kk + tig]);
                uint32_t a2 = __float_as_uint(As[m][kk + tig + 4]);
                uint32_t a3 = __float_as_uint(As[m + 8][kk + tig + 4]);
                #pragma unroll
                for (int nf = 0; nf < 4; nf++)
                    mma_tf32(acc[mf][nf], a0, a1, a2, a3, b[nf][0], b[nf][1]);
            }
        }
        __syncthreads();
    }

    // Epilogue: c0/c1 at (row gid, col 2tig/2tig+1), c2/c3 at row gid+8.
    #pragma unroll
    for (int mf = 0; mf < 4; mf++) {
        #pragma unroll
        for (int nf = 0; nf < 4; nf++) {
            const int cc = bn + wn + nf * 8 + 2 * tig;
            float bx = 0.f, by = 0.f;
            if (bias) { bx = bias[cc]; by = bias[cc + 1]; }
            #pragma unroll
            for (int h = 0; h < 2; h++) {
                const int row = bm + wm + mf * 16 + gid + h * 8;
                float v0 = acc[mf][nf][2 * h + 0] * alpha + bx;
                float v1 = acc[mf][nf][2 * h + 1] * alpha + by;
                if (relu) { v0 = fmaxf(v0, 0.f); v1 = fmaxf(v1, 0.f); }
                if (resid) {
                    float2 rr = *(const float2*)(resid + (size_t)row * N + cc);
                    v0 += rr.x; v1 += rr.y;
                }
                float2 ov = { v0, v1 };
                *(float2*)(C + (size_t)row * N + cc) = ov;
            }
        }
    }
}

// ---------------------------------------------------------------------------
// Transpose (rows x cols) -> (cols x rows), 32x32 tiles
// ---------------------------------------------------------------------------
__global__ void transpose_kernel(const float* __restrict__ in, float* __restrict__ out,
                                 int R, int C) {
    __shared__ float tile[32][33];
    const int c0 = blockIdx.x * 32;
    const int r0 = blockIdx.y * 32;
    for (int dy = threadIdx.y; dy < 32; dy += 8)
        tile[dy][threadIdx.x] = in[(size_t)(r0 + dy) * C + c0 + threadIdx.x];
    __syncthreads();
    for (int dy = threadIdx.y; dy < 32; dy += 8)
        out[(size_t)(c0 + dy) * R + r0 + threadIdx.x] = tile[threadIdx.x][dy];
}

// ---------------------------------------------------------------------------
// Softmax over the slots axis (i), per (b, j) column. attn laid out [B*N, J].
// ---------------------------------------------------------------------------
__global__ void colsoftmax_kernel(float* __restrict__ attn) {
    const int b = blockIdx.y;
    const int t = threadIdx.x;          // 0..127
    const int lane = t & 31;
    const int r = t >> 5;               // 0..3
    const int j = blockIdx.x * 32 + lane;
    float* base = attn + (size_t)b * NN * JJ;

    float m = -3.0e38f, s = 0.f;
    for (int i = r; i < NN; i += 4) {
        float x = base[(size_t)i * JJ + j];
        float nm = fmaxf(m, x);
        s = s * expf(m - nm) + expf(x - nm);
        m = nm;
    }
    __shared__ float sm[4][32], ss[4][32], gm[32], gs[32];
    sm[r][lane] = m;
    ss[r][lane] = s;
    __syncthreads();
    if (r == 0) {
        float M = sm[0][lane];
        #pragma unroll
        for (int p = 1; p < 4; p++) M = fmaxf(M, sm[p][lane]);
        float S = 0.f;
        #pragma unroll
        for (int p = 0; p < 4; p++) S += ss[p][lane] * expf(sm[p][lane] - M);
        gm[lane] = M;
        gs[lane] = 1.f / S;
    }
    __syncthreads();
    const float M = gm[lane], invS = gs[lane];
    for (int i = r; i < NN; i += 4) {
        size_t o = (size_t)i * JJ + j;
        base[o] = expf(base[o] - M) * invS + EPS;
    }
}

// ---------------------------------------------------------------------------
// Row renormalization over j: attn[row, :] /= sum_j attn[row, j]
// ---------------------------------------------------------------------------
__global__ void rownorm_kernel(float* __restrict__ attn) {
    const int row = blockIdx.x;
    float* a = attn + (size_t)row * JJ;
    float s = 0.f;
    for (int i = threadIdx.x; i < JJ; i += 128) s += a[i];
    s = warp_sum(s);
    __shared__ float ws[4];
    if ((threadIdx.x & 31) == 0) ws[threadIdx.x >> 5] = s;
    __syncthreads();
    const float inv = 1.f / (ws[0] + ws[1] + ws[2] + ws[3]);
    for (int i = threadIdx.x; i < JJ; i += 128) a[i] *= inv;
}

// ---------------------------------------------------------------------------
// GRU cell elementwise (torch gate order r, z, n). In-place slots update.
// ---------------------------------------------------------------------------
__global__ void gru_kernel(const float* __restrict__ gi, const float* __restrict__ gh,
                           float* __restrict__ slots) {
    const int idx = blockIdx.x * blockDim.x + threadIdx.x;  // 0 .. MM*DD-1
    const int m = idx >> 10;
    const int d = idx & 1023;
    const size_t o = (size_t)m * (3 * DD) + d;
    const float r = 1.f / (1.f + expf(-(gi[o] + gh[o])));
    const float z = 1.f / (1.f + expf(-(gi[o + DD] + gh[o + DD])));
    const float n = tanhf(gi[o + 2 * DD] + r * gh[o + 2 * DD]);
    const float h = slots[idx];
    slots[idx] = (1.f - z) * n + z * h;
}

// ---------------------------------------------------------------------------
// Launch
// ---------------------------------------------------------------------------
static inline void gemm(const float* A, const float* B, float* C, int M, int N, int K,
                        const float* bias, const float* resid, float alpha, int relu) {
    dim3 grid(N / 128, M / 128);
    gemm_tc_kernel<<<grid, 256>>>(A, B, C, M, N, K, bias, resid, alpha, relu);
}

extern "C" void kernel_launch(void* const* d_in, const int* in_sizes, int n_in,
                              void* d_out, int out_size) {
    const float* inputs = (const float*)d_in[0];
    const float* texts  = (const float*)d_in[1];
    const float* Wq   = (const float*)d_in[2];  const float* bq   = (const float*)d_in[3];
    const float* Wk   = (const float*)d_in[4];  const float* bk   = (const float*)d_in[5];
    const float* Wv   = (const float*)d_in[6];  const float* bv   = (const float*)d_in[7];
    const float* W_ih = (const float*)d_in[8];  const float* b_ih = (const float*)d_in[9];
    const float* W_hh = (const float*)d_in[10]; const float* b_hh = (const float*)d_in[11];
    const float* W1   = (const float*)d_in[12]; const float* b1   = (const float*)d_in[13];
    const float* W2   = (const float*)d_in[14]; const float* b2   = (const float*)d_in[15];
    const float* gin  = (const float*)d_in[16]; const float* bein = (const float*)d_in[17];
    const float* gsl  = (const float*)d_in[18]; const float* besl = (const float*)d_in[19];
    const float* gff  = (const float*)d_in[20]; const float* beff = (const float*)d_in[21];

    float *txn, *k, *v, *vT, *slots, *lnb, *q, *attn, *upd, *gi, *gh, *hid;
    cudaGetSymbolAddress((void**)&txn,  g_txn);
    cudaGetSymbolAddress((void**)&k,    g_k);
    cudaGetSymbolAddress((void**)&v,    g_v);
    cudaGetSymbolAddress((void**)&vT,   g_vT);
    cudaGetSymbolAddress((void**)&slots,g_slots);
    cudaGetSymbolAddress((void**)&lnb,  g_ln);
    cudaGetSymbolAddress((void**)&q,    g_q);
    cudaGetSymbolAddress((void**)&attn, g_attn);
    cudaGetSymbolAddress((void**)&upd,  g_upd);
    cudaGetSymbolAddress((void**)&gi,   g_gi);
    cudaGetSymbolAddress((void**)&gh,   g_gh);
    cudaGetSymbolAddress((void**)&hid,  g_hid);

    // slots = inputs
    cudaMemcpyAsync(slots, inputs, (size_t)MM * DD * sizeof(float),
                    cudaMemcpyDeviceToDevice);

    // texts_n = LN(texts); k = texts_n @ Wk^T + bk; v likewise; vT = v^T
    ln_kernel<<<JJ, 256>>>(texts, txn, gin, bein);
    gemm(txn, Wk, k, JJ, DD, DD, bk, 0, 1.f, 0);
    gemm(txn, Wv, v, JJ, DD, DD, bv, 0, 1.f, 0);
    transpose_kernel<<<dim3(DD / 32, JJ / 32), dim3(32, 8)>>>(v, vT, JJ, DD);

    for (int it = 0; it < 3; it++) {
        // q = LN(slots) @ Wq^T + bq
        ln_kernel<<<MM, 256>>>(slots, lnb, gsl, besl);
        gemm(lnb, Wq, q, MM, DD, DD, bq, 0, 1.f, 0);

        // dots = q @ k^T * SCALE   -> attn buffer [MM, JJ]
        gemm(q, k, attn, MM, JJ, DD, 0, 0, SCALE, 0);

        // softmax over slots axis (+EPS), then renormalize over j
        colsoftmax_kernel<<<dim3(JJ / 32, BB), 128>>>(attn);
        rownorm_kernel<<<MM, 128>>>(attn);

        // updates = attn @ v  (via vT, NT form)
        gemm(attn, vT, upd, MM, DD, JJ, 0, 0, 1.f, 0);

        // GRU gates
        gemm(upd,   W_ih, gi, MM, 3 * DD, DD, b_ih, 0, 1.f, 0);
        gemm(slots, W_hh, gh, MM, 3 * DD, DD, b_hh, 0, 1.f, 0);
        gru_kernel<<<(MM * DD) / 256, 256>>>(gi, gh, slots);

        // FF: slots += relu(LN(slots) @ W1^T + b1) @ W2^T + b2
        ln_kernel<<<MM, 256>>>(slots, lnb, gff, beff);
        gemm(lnb, W1, hid, MM, HH, DD, b1, 0, 1.f, 1);
        float* outp = (it == 2) ? (float*)d_out : slots;
        gemm(hid, W2, outp, MM, DD, HH, b2, slots, 1.f, 0);
    }
}

// round 8
// speedup vs baseline: 4.9338x; 1.4866x over previous
#include <cuda_runtime.h>
#include <cuda_fp16.h>
#include <math.h>
#include <stdint.h>

// Problem constants
#define BB 64
#define NN 128
#define JJ 512
#define DD 1024
#define HH 4096
#define MM (BB * NN)          // 8192 rows
#define SCALE 0.03125f        // 1024^-0.5
#define EPS 1e-8f
#define LN_EPS 1e-5f

// ---------------------------------------------------------------------------
// Scratch (device globals; no allocations allowed)
// ---------------------------------------------------------------------------
__device__ float g_txn [JJ * DD];
__device__ float g_k   [JJ * DD];
__device__ float g_v   [JJ * DD];
__device__ float g_vT  [DD * JJ];
__device__ float g_slots[MM * DD];
__device__ float g_ln  [MM * DD];
__device__ float g_q   [MM * DD];
__device__ float g_attn[MM * JJ];
__device__ float g_upd [MM * DD];
__device__ float g_gi  [MM * 3 * DD];
__device__ float g_gh  [MM * 3 * DD];
__device__ float g_hid [MM * HH];

// ---------------------------------------------------------------------------
// Helpers
// ---------------------------------------------------------------------------
__device__ __forceinline__ float warp_sum(float v) {
    #pragma unroll
    for (int o = 16; o; o >>= 1) v += __shfl_xor_sync(0xFFFFFFFFu, v, o);
    return v;
}

// m16n8k16 fp16 MMA, fp32 accumulate (sm_80+ baseline; legal on compute_103)
__device__ __forceinline__ void mma_f16(float* c,
                                        uint32_t a0, uint32_t a1, uint32_t a2, uint32_t a3,
                                        uint32_t b0, uint32_t b1) {
    asm volatile(
        "mma.sync.aligned.m16n8k16.row.col.f32.f16.f16.f32 "
        "{%0,%1,%2,%3}, {%4,%5,%6,%7}, {%8,%9}, {%0,%1,%2,%3};"
        : "+f"(c[0]), "+f"(c[1]), "+f"(c[2]), "+f"(c[3])
        : "r"(a0), "r"(a1), "r"(a2), "r"(a3), "r"(b0), "r"(b1));
}

// ---------------------------------------------------------------------------
// LayerNorm: one block per row, D = 1024, 256 threads (1 float4 / thread)
// ---------------------------------------------------------------------------
__global__ void ln_kernel(const float* __restrict__ x, float* __restrict__ y,
                          const float* __restrict__ g, const float* __restrict__ b) {
    const int row = blockIdx.x;
    const int t = threadIdx.x;
    const float4* xr = (const float4*)(x + (size_t)row * DD);
    float4 v = xr[t];
    float s = v.x + v.y + v.z + v.w;
    float q = v.x * v.x + v.y * v.y + v.z * v.z + v.w * v.w;
    s = warp_sum(s);
    q = warp_sum(q);
    __shared__ float s1[8], s2[8];
    if ((t & 31) == 0) { s1[t >> 5] = s; s2[t >> 5] = q; }
    __syncthreads();
    float S = 0.f, Q = 0.f;
    #pragma unroll
    for (int w = 0; w < 8; w++) { S += s1[w]; Q += s2[w]; }
    const float mean = S * (1.f / DD);
    const float var  = Q * (1.f / DD) - mean * mean;
    const float inv  = rsqrtf(var + LN_EPS);
    float4 gv = ((const float4*)g)[t];
    float4 bv = ((const float4*)b)[t];
    float4 o;
    o.x = (v.x - mean) * inv * gv.x + bv.x;
    o.y = (v.y - mean) * inv * gv.y + bv.y;
    o.z = (v.z - mean) * inv * gv.z + bv.z;
    o.w = (v.w - mean) * inv * gv.w + bv.w;
    ((float4*)(y + (size_t)row * DD))[t] = o;
}

// ---------------------------------------------------------------------------
// Tensor-core FP16 NT GEMM: C[M,N] = alpha*A[M,K]@B[N,K]^T (+bias)(relu)(+resid)
// CTA tile 128x128, BK=32, 256 threads (8 warps, warp tile 64x32).
// mma.sync.m16n8k16 f16, fp32 accumulate. M,N%128==0, K%32==0.
// Operands RN-rounded to fp16 at staging (10 mantissa bits == tf32).
// ---------------------------------------------------------------------------
#define BK 32
#define LDPH 40    // SMEM row stride in halves (32 + 8 pad) -> conflict-free

__global__ __launch_bounds__(256, 2)
void gemm_tc_kernel(const float* __restrict__ A, const float* __restrict__ Bw,
                    float* __restrict__ C, int M, int N, int K,
                    const float* __restrict__ bias, const float* __restrict__ resid,
                    float alpha, int relu) {
    __shared__ __align__(16) __half As[128][LDPH];
    __shared__ __align__(16) __half Bs[128][LDPH];

    const int tid  = threadIdx.x;
    const int warp = tid >> 5;
    const int lane = tid & 31;
    const int gid  = lane >> 2;          // 0..7
    const int tig  = lane & 3;           // 0..3
    const int wm = (warp >> 2) * 64;     // warp m-offset (0 or 64)
    const int wn = (warp & 3) * 32;      // warp n-offset (0,32,64,96)

    const int bm = blockIdx.y * 128;
    const int bn = blockIdx.x * 128;

    // Staging map: 256 threads x 4 slots cover 128 rows x 8 float4-groups
    const int sr0 = tid >> 3;            // base row (advance by 32 per p)
    const int sf4 = tid & 7;             // float4 group in the 32-wide row

    float acc[4][4][4];
    #pragma unroll
    for (int mf = 0; mf < 4; mf++)
        #pragma unroll
        for (int nf = 0; nf < 4; nf++)
            #pragma unroll
            for (int u = 0; u < 4; u++) acc[mf][nf][u] = 0.f;

    const int nch = K >> 5;

    float4 Ar[4], Br[4];
    // prefetch chunk 0
    #pragma unroll
    for (int p = 0; p < 4; p++) {
        const int r = sr0 + p * 32;
        Ar[p] = *(const float4*)(A  + (size_t)(bm + r) * K + sf4 * 4);
        Br[p] = *(const float4*)(Bw + (size_t)(bn + r) * K + sf4 * 4);
    }

    for (int c = 0; c < nch; c++) {
        // store prefetched chunk (fp32 -> fp16 RN) into SMEM
        #pragma unroll
        for (int p = 0; p < 4; p++) {
            const int r = sr0 + p * 32;
            __half2 a01 = __floats2half2_rn(Ar[p].x, Ar[p].y);
            __half2 a23 = __floats2half2_rn(Ar[p].z, Ar[p].w);
            __half2 b01 = __floats2half2_rn(Br[p].x, Br[p].y);
            __half2 b23 = __floats2half2_rn(Br[p].z, Br[p].w);
            *(uint2*)(&As[r][sf4 * 4]) =
                make_uint2(*(uint32_t*)&a01, *(uint32_t*)&a23);
            *(uint2*)(&Bs[r][sf4 * 4]) =
                make_uint2(*(uint32_t*)&b01, *(uint32_t*)&b23);
        }
        __syncthreads();

        // issue next chunk's global loads (in flight under the MMAs)
        if (c + 1 < nch) {
            const int k0 = (c + 1) << 5;
            #pragma unroll
            for (int p = 0; p < 4; p++) {
                const int r = sr0 + p * 32;
                Ar[p] = *(const float4*)(A  + (size_t)(bm + r) * K + k0 + sf4 * 4);
                Br[p] = *(const float4*)(Bw + (size_t)(bn + r) * K + k0 + sf4 * 4);
            }
        }

        // compute: 2 k-steps of m16n8k16
        #pragma unroll
        for (int ks = 0; ks < 2; ks++) {
            const int kk = ks * 16;
            uint32_t b[4][2];
            #pragma unroll
            for (int nf = 0; nf < 4; nf++) {
                const int n = wn + nf * 8 + gid;
                b[nf][0] = *(const uint32_t*)(&Bs[n][kk + 2 * tig]);
                b[nf][1] = *(const uint32_t*)(&Bs[n][kk + 2 * tig + 8]);
            }
            #pragma unroll
            for (int mf = 0; mf < 4; mf++) {
                const int m = wm + mf * 16 + gid;
                uint32_t a0 = *(const uint32_t*)(&As[m][kk + 2 * tig]);
                uint32_t a1 = *(const uint32_t*)(&As[m + 8][kk + 2 * tig]);
                uint32_t a2 = *(const uint32_t*)(&As[m][kk + 2 * tig + 8]);
                uint32_t a3 = *(const uint32_t*)(&As[m + 8][kk + 2 * tig + 8]);
                #pragma unroll
                for (int nf = 0; nf < 4; nf++)
                    mma_f16(acc[mf][nf], a0, a1, a2, a3, b[nf][0], b[nf][1]);
            }
        }
        __syncthreads();
    }

    // Epilogue: c0/c1 at (row gid, col 2tig/2tig+1), c2/c3 at row gid+8.
    #pragma unroll
    for (int mf = 0; mf < 4; mf++) {
        #pragma unroll
        for (int nf = 0; nf < 4; nf++) {
            const int cc = bn + wn + nf * 8 + 2 * tig;
            float bx = 0.f, by = 0.f;
            if (bias) { bx = bias[cc]; by = bias[cc + 1]; }
            #pragma unroll
            for (int h = 0; h < 2; h++) {
                const int row = bm + wm + mf * 16 + gid + h * 8;
                float v0 = acc[mf][nf][2 * h + 0] * alpha + bx;
                float v1 = acc[mf][nf][2 * h + 1] * alpha + by;
                if (relu) { v0 = fmaxf(v0, 0.f); v1 = fmaxf(v1, 0.f); }
                if (resid) {
                    float2 rr = *(const float2*)(resid + (size_t)row * N + cc);
                    v0 += rr.x; v1 += rr.y;
                }
                float2 ov = { v0, v1 };
                *(float2*)(C + (size_t)row * N + cc) = ov;
            }
        }
    }
}

// ---------------------------------------------------------------------------
// Transpose (rows x cols) -> (cols x rows), 32x32 tiles
// ---------------------------------------------------------------------------
__global__ void transpose_kernel(const float* __restrict__ in, float* __restrict__ out,
                                 int R, int C) {
    __shared__ float tile[32][33];
    const int c0 = blockIdx.x * 32;
    const int r0 = blockIdx.y * 32;
    for (int dy = threadIdx.y; dy < 32; dy += 8)
        tile[dy][threadIdx.x] = in[(size_t)(r0 + dy) * C + c0 + threadIdx.x];
    __syncthreads();
    for (int dy = threadIdx.y; dy < 32; dy += 8)
        out[(size_t)(c0 + dy) * R + r0 + threadIdx.x] = tile[threadIdx.x][dy];
}

// ---------------------------------------------------------------------------
// Softmax over the slots axis (i), per (b, j) column. attn laid out [B*N, J].
// ---------------------------------------------------------------------------
__global__ void colsoftmax_kernel(float* __restrict__ attn) {
    const int b = blockIdx.y;
    const int t = threadIdx.x;          // 0..127
    const int lane = t & 31;
    const int r = t >> 5;               // 0..3
    const int j = blockIdx.x * 32 + lane;
    float* base = attn + (size_t)b * NN * JJ;

    float m = -3.0e38f, s = 0.f;
    for (int i = r; i < NN; i += 4) {
        float x = base[(size_t)i * JJ + j];
        float nm = fmaxf(m, x);
        s = s * expf(m - nm) + expf(x - nm);
        m = nm;
    }
    __shared__ float sm[4][32], ss[4][32], gm[32], gs[32];
    sm[r][lane] = m;
    ss[r][lane] = s;
    __syncthreads();
    if (r == 0) {
        float M = sm[0][lane];
        #pragma unroll
        for (int p = 1; p < 4; p++) M = fmaxf(M, sm[p][lane]);
        float S = 0.f;
        #pragma unroll
        for (int p = 0; p < 4; p++) S += ss[p][lane] * expf(sm[p][lane] - M);
        gm[lane] = M;
        gs[lane] = 1.f / S;
    }
    __syncthreads();
    const float M = gm[lane], invS = gs[lane];
    for (int i = r; i < NN; i += 4) {
        size_t o = (size_t)i * JJ + j;
        base[o] = expf(base[o] - M) * invS + EPS;
    }
}

// ---------------------------------------------------------------------------
// Row renormalization over j: attn[row, :] /= sum_j attn[row, j]
// ---------------------------------------------------------------------------
__global__ void rownorm_kernel(float* __restrict__ attn) {
    const int row = blockIdx.x;
    float* a = attn + (size_t)row * JJ;
    float s = 0.f;
    for (int i = threadIdx.x; i < JJ; i += 128) s += a[i];
    s = warp_sum(s);
    __shared__ float ws[4];
    if ((threadIdx.x & 31) == 0) ws[threadIdx.x >> 5] = s;
    __syncthreads();
    const float inv = 1.f / (ws[0] + ws[1] + ws[2] + ws[3]);
    for (int i = threadIdx.x; i < JJ; i += 128) a[i] *= inv;
}

// ---------------------------------------------------------------------------
// GRU cell elementwise (torch gate order r, z, n). In-place slots update.
// ---------------------------------------------------------------------------
__global__ void gru_kernel(const float* __restrict__ gi, const float* __restrict__ gh,
                           float* __restrict__ slots) {
    const int idx = blockIdx.x * blockDim.x + threadIdx.x;  // 0 .. MM*DD-1
    const int m = idx >> 10;
    const int d = idx & 1023;
    const size_t o = (size_t)m * (3 * DD) + d;
    const float r = 1.f / (1.f + expf(-(gi[o] + gh[o])));
    const float z = 1.f / (1.f + expf(-(gi[o + DD] + gh[o + DD])));
    const float n = tanhf(gi[o + 2 * DD] + r * gh[o + 2 * DD]);
    const float h = slots[idx];
    slots[idx] = (1.f - z) * n + z * h;
}

// ---------------------------------------------------------------------------
// Launch
// ---------------------------------------------------------------------------
static inline void gemm(const float* A, const float* B, float* C, int M, int N, int K,
                        const float* bias, const float* resid, float alpha, int relu) {
    dim3 grid(N / 128, M / 128);
    gemm_tc_kernel<<<grid, 256>>>(A, B, C, M, N, K, bias, resid, alpha, relu);
}

extern "C" void kernel_launch(void* const* d_in, const int* in_sizes, int n_in,
                              void* d_out, int out_size) {
    const float* inputs = (const float*)d_in[0];
    const float* texts  = (const float*)d_in[1];
    const float* Wq   = (const float*)d_in[2];  const float* bq   = (const float*)d_in[3];
    const float* Wk   = (const float*)d_in[4];  const float* bk   = (const float*)d_in[5];
    const float* Wv   = (const float*)d_in[6];  const float* bv   = (const float*)d_in[7];
    const float* W_ih = (const float*)d_in[8];  const float* b_ih = (const float*)d_in[9];
    const float* W_hh = (const float*)d_in[10]; const float* b_hh = (const float*)d_in[11];
    const float* W1   = (const float*)d_in[12]; const float* b1   = (const float*)d_in[13];
    const float* W2   = (const float*)d_in[14]; const float* b2   = (const float*)d_in[15];
    const float* gin  = (const float*)d_in[16]; const float* bein = (const float*)d_in[17];
    const float* gsl  = (const float*)d_in[18]; const float* besl = (const float*)d_in[19];
    const float* gff  = (const float*)d_in[20]; const float* beff = (const float*)d_in[21];

    float *txn, *k, *v, *vT, *slots, *lnb, *q, *attn, *upd, *gi, *gh, *hid;
    cudaGetSymbolAddress((void**)&txn,  g_txn);
    cudaGetSymbolAddress((void**)&k,    g_k);
    cudaGetSymbolAddress((void**)&v,    g_v);
    cudaGetSymbolAddress((void**)&vT,   g_vT);
    cudaGetSymbolAddress((void**)&slots,g_slots);
    cudaGetSymbolAddress((void**)&lnb,  g_ln);
    cudaGetSymbolAddress((void**)&q,    g_q);
    cudaGetSymbolAddress((void**)&attn, g_attn);
    cudaGetSymbolAddress((void**)&upd,  g_upd);
    cudaGetSymbolAddress((void**)&gi,   g_gi);
    cudaGetSymbolAddress((void**)&gh,   g_gh);
    cudaGetSymbolAddress((void**)&hid,  g_hid);

    // slots = inputs
    cudaMemcpyAsync(slots, inputs, (size_t)MM * DD * sizeof(float),
                    cudaMemcpyDeviceToDevice);

    // texts_n = LN(texts); k = texts_n @ Wk^T + bk; v likewise; vT = v^T
    ln_kernel<<<JJ, 256>>>(texts, txn, gin, bein);
    gemm(txn, Wk, k, JJ, DD, DD, bk, 0, 1.f, 0);
    gemm(txn, Wv, v, JJ, DD, DD, bv, 0, 1.f, 0);
    transpose_kernel<<<dim3(DD / 32, JJ / 32), dim3(32, 8)>>>(v, vT, JJ, DD);

    for (int it = 0; it < 3; it++) {
        // q = LN(slots) @ Wq^T + bq
        ln_kernel<<<MM, 256>>>(slots, lnb, gsl, besl);
        gemm(lnb, Wq, q, MM, DD, DD, bq, 0, 1.f, 0);

        // dots = q @ k^T * SCALE   -> attn buffer [MM, JJ]
        gemm(q, k, attn, MM, JJ, DD, 0, 0, SCALE, 0);

        // softmax over slots axis (+EPS), then renormalize over j
        colsoftmax_kernel<<<dim3(JJ / 32, BB), 128>>>(attn);
        rownorm_kernel<<<MM, 128>>>(attn);

        // updates = attn @ v  (via vT, NT form)
        gemm(attn, vT, upd, MM, DD, JJ, 0, 0, 1.f, 0);

        // GRU gates
        gemm(upd,   W_ih, gi, MM, 3 * DD, DD, b_ih, 0, 1.f, 0);
        gemm(slots, W_hh, gh, MM, 3 * DD, DD, b_hh, 0, 1.f, 0);
        gru_kernel<<<(MM * DD) / 256, 256>>>(gi, gh, slots);

        // FF: slots += relu(LN(slots) @ W1^T + b1) @ W2^T + b2
        ln_kernel<<<MM, 256>>>(slots, lnb, gff, beff);
        gemm(lnb, W1, hid, MM, HH, DD, b1, 0, 1.f, 1);
        float* outp = (it == 2) ? (float*)d_out : slots;
        gemm(hid, W2, outp, MM, DD, HH, b2, slots, 1.f, 0);
    }
}

// round 9
// speedup vs baseline: 5.4055x; 1.0956x over previous
#include <cuda_runtime.h>
#include <cuda_fp16.h>
#include <math.h>
#include <stdint.h>

// Problem constants
#define BB 64
#define NN 128
#define JJ 512
#define DD 1024
#define HH 4096
#define MM (BB * NN)          // 8192 rows
#define SCALE 0.03125f        // 1024^-0.5
#define EPS 1e-8f
#define LN_EPS 1e-5f

// ---------------------------------------------------------------------------
// Scratch (device globals; no allocations allowed)
// ---------------------------------------------------------------------------
__device__ float g_txn [JJ * DD];
__device__ float g_k   [JJ * DD];
__device__ float g_v   [JJ * DD];
__device__ float g_vT  [DD * JJ];
__device__ float g_slots[MM * DD];
__device__ float g_ln  [MM * DD];
__device__ float g_q   [MM * DD];
__device__ float g_attn[MM * JJ];
__device__ float g_upd [MM * DD];
__device__ float g_gi  [MM * 3 * DD];
__device__ float g_gh  [MM * 3 * DD];
__device__ float g_hid [MM * HH];

// ---------------------------------------------------------------------------
// Helpers
// ---------------------------------------------------------------------------
__device__ __forceinline__ float warp_sum(float v) {
    #pragma unroll
    for (int o = 16; o; o >>= 1) v += __shfl_xor_sync(0xFFFFFFFFu, v, o);
    return v;
}

__device__ __forceinline__ uint32_t smem_u32(const void* p) {
    uint32_t a;
    asm("{ .reg .u64 t; cvta.to.shared.u64 t, %1; cvt.u32.u64 %0, t; }"
        : "=r"(a) : "l"(p));
    return a;
}

// m16n8k16 fp16 MMA, fp32 accumulate (sm_80+ baseline; legal on compute_103)
__device__ __forceinline__ void mma_f16(float* c,
                                        uint32_t a0, uint32_t a1, uint32_t a2, uint32_t a3,
                                        uint32_t b0, uint32_t b1) {
    asm volatile(
        "mma.sync.aligned.m16n8k16.row.col.f32.f16.f16.f32 "
        "{%0,%1,%2,%3}, {%4,%5,%6,%7}, {%8,%9}, {%0,%1,%2,%3};"
        : "+f"(c[0]), "+f"(c[1]), "+f"(c[2]), "+f"(c[3])
        : "r"(a0), "r"(a1), "r"(a2), "r"(a3), "r"(b0), "r"(b1));
}

// ldmatrix x4: four 8x8 b16 fragments (sm_75+ baseline)
__device__ __forceinline__ void ldsm_x4(uint32_t& r0, uint32_t& r1,
                                        uint32_t& r2, uint32_t& r3, uint32_t addr) {
    asm volatile("ldmatrix.sync.aligned.m8n8.x4.shared.b16 {%0,%1,%2,%3}, [%4];"
                 : "=r"(r0), "=r"(r1), "=r"(r2), "=r"(r3) : "r"(addr));
}

// ---------------------------------------------------------------------------
// LayerNorm: one block per row, D = 1024, 256 threads (1 float4 / thread)
// ---------------------------------------------------------------------------
__global__ void ln_kernel(const float* __restrict__ x, float* __restrict__ y,
                          const float* __restrict__ g, const float* __restrict__ b) {
    const int row = blockIdx.x;
    const int t = threadIdx.x;
    const float4* xr = (const float4*)(x + (size_t)row * DD);
    float4 v = xr[t];
    float s = v.x + v.y + v.z + v.w;
    float q = v.x * v.x + v.y * v.y + v.z * v.z + v.w * v.w;
    s = warp_sum(s);
    q = warp_sum(q);
    __shared__ float s1[8], s2[8];
    if ((t & 31) == 0) { s1[t >> 5] = s; s2[t >> 5] = q; }
    __syncthreads();
    float S = 0.f, Q = 0.f;
    #pragma unroll
    for (int w = 0; w < 8; w++) { S += s1[w]; Q += s2[w]; }
    const float mean = S * (1.f / DD);
    const float var  = Q * (1.f / DD) - mean * mean;
    const float inv  = rsqrtf(var + LN_EPS);
    float4 gv = ((const float4*)g)[t];
    float4 bv = ((const float4*)b)[t];
    float4 o;
    o.x = (v.x - mean) * inv * gv.x + bv.x;
    o.y = (v.y - mean) * inv * gv.y + bv.y;
    o.z = (v.z - mean) * inv * gv.z + bv.z;
    o.w = (v.w - mean) * inv * gv.w + bv.w;
    ((float4*)(y + (size_t)row * DD))[t] = o;
}

// ---------------------------------------------------------------------------
// Tensor-core FP16 NT GEMM: C[M,N] = alpha*A[M,K]@B[N,K]^T (+bias)(relu)(+resid)
// CTA tile 128x128, BK=32, 256 threads (8 warps, warp tile 64x32).
// mma.sync.m16n8k16 f16 + ldmatrix.x4 fragment loads. fp32 accumulate.
// M,N%128==0, K%32==0. Operands RN-rounded to fp16 at staging.
// ---------------------------------------------------------------------------
#define BK 32
#define LDPH 40    // SMEM row stride in halves (32 + 8 pad) -> conflict-free

__global__ __launch_bounds__(256, 2)
void gemm_tc_kernel(const float* __restrict__ A, const float* __restrict__ Bw,
                    float* __restrict__ C, int M, int N, int K,
                    const float* __restrict__ bias, const float* __restrict__ resid,
                    float alpha, int relu) {
    __shared__ __align__(16) __half As[128][LDPH];
    __shared__ __align__(16) __half Bs[128][LDPH];

    const int tid  = threadIdx.x;
    const int warp = tid >> 5;
    const int lane = tid & 31;
    const int gid  = lane >> 2;          // 0..7
    const int tig  = lane & 3;           // 0..3
    const int wm = (warp >> 2) * 64;     // warp m-offset (0 or 64)
    const int wn = (warp & 3) * 32;      // warp n-offset (0,32,64,96)

    const int bm = blockIdx.y * 128;
    const int bn = blockIdx.x * 128;

    // Staging map: 256 threads x 4 slots cover 128 rows x 8 float4-groups
    const int sr0 = tid >> 3;            // base row (advance by 32 per p)
    const int sf4 = tid & 7;             // float4 group in the 32-wide row

    // ldmatrix per-lane base addresses.
    // A x4 at (mf, ks): matrices {rows m..m+16} x {k kk..kk+16} ->
    //   lane row = wm + (lane & 15), lane col = (lane >> 4) * 8
    const uint32_t a_base =
        smem_u32(&As[wm + (lane & 15)][(lane >> 4) * 8]);
    // B x4 at (p, ks): covers nf=2p (rows n0..n0+8) and nf=2p+1 (n0+8..n0+16):
    //   lane row = wn + (lane>>4)*8 + (lane&7), lane col = ((lane>>3)&1)*8
    const uint32_t b_base =
        smem_u32(&Bs[wn + ((lane >> 4) << 3) + (lane & 7)][((lane >> 3) & 1) * 8]);

    float acc[4][4][4];
    #pragma unroll
    for (int mf = 0; mf < 4; mf++)
        #pragma unroll
        for (int nf = 0; nf < 4; nf++)
            #pragma unroll
            for (int u = 0; u < 4; u++) acc[mf][nf][u] = 0.f;

    const int nch = K >> 5;

    float4 Ar[4], Br[4];
    // prefetch chunk 0
    #pragma unroll
    for (int p = 0; p < 4; p++) {
        const int r = sr0 + p * 32;
        Ar[p] = *(const float4*)(A  + (size_t)(bm + r) * K + sf4 * 4);
        Br[p] = *(const float4*)(Bw + (size_t)(bn + r) * K + sf4 * 4);
    }

    for (int c = 0; c < nch; c++) {
        // store prefetched chunk (fp32 -> fp16 RN) into SMEM
        #pragma unroll
        for (int p = 0; p < 4; p++) {
            const int r = sr0 + p * 32;
            __half2 a01 = __floats2half2_rn(Ar[p].x, Ar[p].y);
            __half2 a23 = __floats2half2_rn(Ar[p].z, Ar[p].w);
            __half2 b01 = __floats2half2_rn(Br[p].x, Br[p].y);
            __half2 b23 = __floats2half2_rn(Br[p].z, Br[p].w);
            *(uint2*)(&As[r][sf4 * 4]) =
                make_uint2(*(uint32_t*)&a01, *(uint32_t*)&a23);
            *(uint2*)(&Bs[r][sf4 * 4]) =
                make_uint2(*(uint32_t*)&b01, *(uint32_t*)&b23);
        }
        __syncthreads();

        // issue next chunk's global loads (in flight under the MMAs)
        if (c + 1 < nch) {
            const int k0 = (c + 1) << 5;
            #pragma unroll
            for (int p = 0; p < 4; p++) {
                const int r = sr0 + p * 32;
                Ar[p] = *(const float4*)(A  + (size_t)(bm + r) * K + k0 + sf4 * 4);
                Br[p] = *(const float4*)(Bw + (size_t)(bn + r) * K + k0 + sf4 * 4);
            }
        }

        // compute: 2 k-steps of m16n8k16, fragments via ldmatrix.x4
        #pragma unroll
        for (int ks = 0; ks < 2; ks++) {
            const uint32_t koff = (uint32_t)(ks * 16 * 2);   // 16 halves
            uint32_t b[4][2];
            ldsm_x4(b[0][0], b[0][1], b[1][0], b[1][1], b_base + koff);
            ldsm_x4(b[2][0], b[2][1], b[3][0], b[3][1],
                    b_base + koff + 16 * LDPH * 2);
            #pragma unroll
            for (int mf = 0; mf < 4; mf++) {
                uint32_t a0, a1, a2, a3;
                ldsm_x4(a0, a1, a2, a3,
                        a_base + koff + (uint32_t)(mf * 16 * LDPH * 2));
                #pragma unroll
                for (int nf = 0; nf < 4; nf++)
                    mma_f16(acc[mf][nf], a0, a1, a2, a3, b[nf][0], b[nf][1]);
            }
        }
        __syncthreads();
    }

    // Epilogue: c0/c1 at (row gid, col 2tig/2tig+1), c2/c3 at row gid+8.
    #pragma unroll
    for (int mf = 0; mf < 4; mf++) {
        #pragma unroll
        for (int nf = 0; nf < 4; nf++) {
            const int cc = bn + wn + nf * 8 + 2 * tig;
            float bx = 0.f, by = 0.f;
            if (bias) { bx = bias[cc]; by = bias[cc + 1]; }
            #pragma unroll
            for (int h = 0; h < 2; h++) {
                const int row = bm + wm + mf * 16 + gid + h * 8;
                float v0 = acc[mf][nf][2 * h + 0] * alpha + bx;
                float v1 = acc[mf][nf][2 * h + 1] * alpha + by;
                if (relu) { v0 = fmaxf(v0, 0.f); v1 = fmaxf(v1, 0.f); }
                if (resid) {
                    float2 rr = *(const float2*)(resid + (size_t)row * N + cc);
                    v0 += rr.x; v1 += rr.y;
                }
                float2 ov = { v0, v1 };
                *(float2*)(C + (size_t)row * N + cc) = ov;
            }
        }
    }
}

// ---------------------------------------------------------------------------
// Transpose (rows x cols) -> (cols x rows), 32x32 tiles
// ---------------------------------------------------------------------------
__global__ void transpose_kernel(const float* __restrict__ in, float* __restrict__ out,
                                 int R, int C) {
    __shared__ float tile[32][33];
    const int c0 = blockIdx.x * 32;
    const int r0 = blockIdx.y * 32;
    for (int dy = threadIdx.y; dy < 32; dy += 8)
        tile[dy][threadIdx.x] = in[(size_t)(r0 + dy) * C + c0 + threadIdx.x];
    __syncthreads();
    for (int dy = threadIdx.y; dy < 32; dy += 8)
        out[(size_t)(c0 + dy) * R + r0 + threadIdx.x] = tile[threadIdx.x][dy];
}

// ---------------------------------------------------------------------------
// Softmax over the slots axis (i), per (b, j) column. attn laid out [B*N, J].
// ---------------------------------------------------------------------------
__global__ void colsoftmax_kernel(float* __restrict__ attn) {
    const int b = blockIdx.y;
    const int t = threadIdx.x;          // 0..127
    const int lane = t & 31;
    const int r = t >> 5;               // 0..3
    const int j = blockIdx.x * 32 + lane;
    float* base = attn + (size_t)b * NN * JJ;

    float m = -3.0e38f, s = 0.f;
    for (int i = r; i < NN; i += 4) {
        float x = base[(size_t)i * JJ + j];
        float nm = fmaxf(m, x);
        s = s * expf(m - nm) + expf(x - nm);
        m = nm;
    }
    __shared__ float sm[4][32], ss[4][32], gm[32], gs[32];
    sm[r][lane] = m;
    ss[r][lane] = s;
    __syncthreads();
    if (r == 0) {
        float M = sm[0][lane];
        #pragma unroll
        for (int p = 1; p < 4; p++) M = fmaxf(M, sm[p][lane]);
        float S = 0.f;
        #pragma unroll
        for (int p = 0; p < 4; p++) S += ss[p][lane] * expf(sm[p][lane] - M);
        gm[lane] = M;
        gs[lane] = 1.f / S;
    }
    __syncthreads();
    const float M = gm[lane], invS = gs[lane];
    for (int i = r; i < NN; i += 4) {
        size_t o = (size_t)i * JJ + j;
        base[o] = expf(base[o] - M) * invS + EPS;
    }
}

// ---------------------------------------------------------------------------
// Row renormalization over j: attn[row, :] /= sum_j attn[row, j]
// ---------------------------------------------------------------------------
__global__ void rownorm_kernel(float* __restrict__ attn) {
    const int row = blockIdx.x;
    float* a = attn + (size_t)row * JJ;
    float s = 0.f;
    for (int i = threadIdx.x; i < JJ; i += 128) s += a[i];
    s = warp_sum(s);
    __shared__ float ws[4];
    if ((threadIdx.x & 31) == 0) ws[threadIdx.x >> 5] = s;
    __syncthreads();
    const float inv = 1.f / (ws[0] + ws[1] + ws[2] + ws[3]);
    for (int i = threadIdx.x; i < JJ; i += 128) a[i] *= inv;
}

// ---------------------------------------------------------------------------
// GRU cell elementwise (torch gate order r, z, n). In-place slots update.
// ---------------------------------------------------------------------------
__global__ void gru_kernel(const float* __restrict__ gi, const float* __restrict__ gh,
                           float* __restrict__ slots) {
    const int idx = blockIdx.x * blockDim.x + threadIdx.x;  // 0 .. MM*DD-1
    const int m = idx >> 10;
    const int d = idx & 1023;
    const size_t o = (size_t)m * (3 * DD) + d;
    const float r = 1.f / (1.f + expf(-(gi[o] + gh[o])));
    const float z = 1.f / (1.f + expf(-(gi[o + DD] + gh[o + DD])));
    const float n = tanhf(gi[o + 2 * DD] + r * gh[o + 2 * DD]);
    const float h = slots[idx];
    slots[idx] = (1.f - z) * n + z * h;
}

// ---------------------------------------------------------------------------
// Launch
// ---------------------------------------------------------------------------
static inline void gemm(const float* A, const float* B, float* C, int M, int N, int K,
                        const float* bias, const float* resid, float alpha, int relu) {
    dim3 grid(N / 128, M / 128);
    gemm_tc_kernel<<<grid, 256>>>(A, B, C, M, N, K, bias, resid, alpha, relu);
}

extern "C" void kernel_launch(void* const* d_in, const int* in_sizes, int n_in,
                              void* d_out, int out_size) {
    const float* inputs = (const float*)d_in[0];
    const float* texts  = (const float*)d_in[1];
    const float* Wq   = (const float*)d_in[2];  const float* bq   = (const float*)d_in[3];
    const float* Wk   = (const float*)d_in[4];  const float* bk   = (const float*)d_in[5];
    const float* Wv   = (const float*)d_in[6];  const float* bv   = (const float*)d_in[7];
    const float* W_ih = (const float*)d_in[8];  const float* b_ih = (const float*)d_in[9];
    const float* W_hh = (const float*)d_in[10]; const float* b_hh = (const float*)d_in[11];
    const float* W1   = (const float*)d_in[12]; const float* b1   = (const float*)d_in[13];
    const float* W2   = (const float*)d_in[14]; const float* b2   = (const float*)d_in[15];
    const float* gin  = (const float*)d_in[16]; const float* bein = (const float*)d_in[17];
    const float* gsl  = (const float*)d_in[18]; const float* besl = (const float*)d_in[19];
    const float* gff  = (const float*)d_in[20]; const float* beff = (const float*)d_in[21];

    float *txn, *k, *v, *vT, *slots, *lnb, *q, *attn, *upd, *gi, *gh, *hid;
    cudaGetSymbolAddress((void**)&txn,  g_txn);
    cudaGetSymbolAddress((void**)&k,    g_k);
    cudaGetSymbolAddress((void**)&v,    g_v);
    cudaGetSymbolAddress((void**)&vT,   g_vT);
    cudaGetSymbolAddress((void**)&slots,g_slots);
    cudaGetSymbolAddress((void**)&lnb,  g_ln);
    cudaGetSymbolAddress((void**)&q,    g_q);
    cudaGetSymbolAddress((void**)&attn, g_attn);
    cudaGetSymbolAddress((void**)&upd,  g_upd);
    cudaGetSymbolAddress((void**)&gi,   g_gi);
    cudaGetSymbolAddress((void**)&gh,   g_gh);
    cudaGetSymbolAddress((void**)&hid,  g_hid);

    // slots = inputs
    cudaMemcpyAsync(slots, inputs, (size_t)MM * DD * sizeof(float),
                    cudaMemcpyDeviceToDevice);

    // texts_n = LN(texts); k = texts_n @ Wk^T + bk; v likewise; vT = v^T
    ln_kernel<<<JJ, 256>>>(texts, txn, gin, bein);
    gemm(txn, Wk, k, JJ, DD, DD, bk, 0, 1.f, 0);
    gemm(txn, Wv, v, JJ, DD, DD, bv, 0, 1.f, 0);
    transpose_kernel<<<dim3(DD / 32, JJ / 32), dim3(32, 8)>>>(v, vT, JJ, DD);

    for (int it = 0; it < 3; it++) {
        // q = LN(slots) @ Wq^T + bq
        ln_kernel<<<MM, 256>>>(slots, lnb, gsl, besl);
        gemm(lnb, Wq, q, MM, DD, DD, bq, 0, 1.f, 0);

        // dots = q @ k^T * SCALE   -> attn buffer [MM, JJ]
        gemm(q, k, attn, MM, JJ, DD, 0, 0, SCALE, 0);

        // softmax over slots axis (+EPS), then renormalize over j
        colsoftmax_kernel<<<dim3(JJ / 32, BB), 128>>>(attn);
        rownorm_kernel<<<MM, 128>>>(attn);

        // updates = attn @ v  (via vT, NT form)
        gemm(attn, vT, upd, MM, DD, JJ, 0, 0, 1.f, 0);

        // GRU gates
        gemm(upd,   W_ih, gi, MM, 3 * DD, DD, b_ih, 0, 1.f, 0);
        gemm(slots, W_hh, gh, MM, 3 * DD, DD, b_hh, 0, 1.f, 0);
        gru_kernel<<<(MM * DD) / 256, 256>>>(gi, gh, slots);

        // FF: slots += relu(LN(slots) @ W1^T + b1) @ W2^T + b2
        ln_kernel<<<MM, 256>>>(slots, lnb, gff, beff);
        gemm(lnb, W1, hid, MM, HH, DD, b1, 0, 1.f, 1);
        float* outp = (it == 2) ? (float*)d_out : slots;
        gemm(hid, W2, outp, MM, DD, HH, b2, slots, 1.f, 0);
    }
}

// round 11
// speedup vs baseline: 6.0058x; 1.1110x over previous
#include <cuda_runtime.h>
#include <cuda_fp16.h>
#include <math.h>
#include <stdint.h>

// Problem constants
#define BB 64
#define NN 128
#define JJ 512
#define DD 1024
#define HH 4096
#define MM (BB * NN)          // 8192 rows
#define SCALE 0.03125f        // 1024^-0.5
#define EPS 1e-8f
#define LN_EPS 1e-5f

// ---------------------------------------------------------------------------
// Scratch (device globals; no allocations allowed)
// ---------------------------------------------------------------------------
__device__ float g_slots[MM * DD];
__device__ float g_attn [MM * JJ];
__device__ float g_gi   [MM * 3 * DD];
__device__ float g_gh   [MM * 3 * DD];

__device__ __align__(16) __half g_txn16 [JJ * DD];
__device__ __align__(16) __half g_k16   [JJ * DD];
__device__ __align__(16) __half g_v16   [JJ * DD];
__device__ __align__(16) __half g_vT16  [DD * JJ];
__device__ __align__(16) __half g_q16   [MM * DD];
__device__ __align__(16) __half g_attn16[MM * JJ];
__device__ __align__(16) __half g_upd16 [MM * DD];
__device__ __align__(16) __half g_hid16 [MM * HH];
__device__ __align__(16) __half g_lnb16 [MM * DD];
__device__ __align__(16) __half g_slots16[MM * DD];
__device__ __align__(16) __half g_Wq16  [DD * DD];
__device__ __align__(16) __half g_Wk16  [DD * DD];
__device__ __align__(16) __half g_Wv16  [DD * DD];
__device__ __align__(16) __half g_Wih16 [3 * DD * DD];
__device__ __align__(16) __half g_Whh16 [3 * DD * DD];
__device__ __align__(16) __half g_W116  [HH * DD];
__device__ __align__(16) __half g_W216  [DD * HH];

// ---------------------------------------------------------------------------
// Helpers
// ---------------------------------------------------------------------------
__device__ __forceinline__ float warp_sum(float v) {
    #pragma unroll
    for (int o = 16; o; o >>= 1) v += __shfl_xor_sync(0xFFFFFFFFu, v, o);
    return v;
}

__device__ __forceinline__ uint32_t smem_u32(const void* p) {
    uint32_t a;
    asm("{ .reg .u64 t; cvta.to.shared.u64 t, %1; cvt.u32.u64 %0, t; }"
        : "=r"(a) : "l"(p));
    return a;
}

// m16n8k16 fp16 MMA, fp32 accumulate (sm_80+ baseline)
__device__ __forceinline__ void mma_f16(float* c,
                                        uint32_t a0, uint32_t a1, uint32_t a2, uint32_t a3,
                                        uint32_t b0, uint32_t b1) {
    asm volatile(
        "mma.sync.aligned.m16n8k16.row.col.f32.f16.f16.f32 "
        "{%0,%1,%2,%3}, {%4,%5,%6,%7}, {%8,%9}, {%0,%1,%2,%3};"
        : "+f"(c[0]), "+f"(c[1]), "+f"(c[2]), "+f"(c[3])
        : "r"(a0), "r"(a1), "r"(a2), "r"(a3), "r"(b0), "r"(b1));
}

__device__ __forceinline__ void ldsm_x4(uint32_t& r0, uint32_t& r1,
                                        uint32_t& r2, uint32_t& r3, uint32_t addr) {
    asm volatile("ldmatrix.sync.aligned.m8n8.x4.shared.b16 {%0,%1,%2,%3}, [%4];"
                 : "=r"(r0), "=r"(r1), "=r"(r2), "=r"(r3) : "r"(addr));
}

#define CP16(smem, gptr) \
    asm volatile("cp.async.cg.shared.global [%0], [%1], 16;" \
                 :: "r"(smem), "l"(gptr))
#define CP_COMMIT() asm volatile("cp.async.commit_group;")
#define CP_WAIT1()  asm volatile("cp.async.wait_group 1;")
#define CP_WAIT0()  asm volatile("cp.async.wait_group 0;")

// ---------------------------------------------------------------------------
// fp32 -> fp16 conversion (n must be a multiple of 4)
// ---------------------------------------------------------------------------
__global__ void f2h_kernel(const float* __restrict__ in, __half* __restrict__ out,
                           int n4) {
    const int i = blockIdx.x * blockDim.x + threadIdx.x;
    if (i < n4) {
        float4 v = ((const float4*)in)[i];
        __half2 h01 = __floats2half2_rn(v.x, v.y);
        __half2 h23 = __floats2half2_rn(v.z, v.w);
        ((uint2*)out)[i] = make_uint2(*(uint32_t*)&h01, *(uint32_t*)&h23);
    }
}

// ---------------------------------------------------------------------------
// LayerNorm: fp32 in -> fp16 out. One block per row, D=1024, 256 threads.
// ---------------------------------------------------------------------------
__global__ void ln_kernel(const float* __restrict__ x, __half* __restrict__ y,
                          const float* __restrict__ g, const float* __restrict__ b) {
    const int row = blockIdx.x;
    const int t = threadIdx.x;
    const float4* xr = (const float4*)(x + (size_t)row * DD);
    float4 v = xr[t];
    float s = v.x + v.y + v.z + v.w;
    float q = v.x * v.x + v.y * v.y + v.z * v.z + v.w * v.w;
    s = warp_sum(s);
    q = warp_sum(q);
    __shared__ float s1[8], s2[8];
    if ((t & 31) == 0) { s1[t >> 5] = s; s2[t >> 5] = q; }
    __syncthreads();
    float S = 0.f, Q = 0.f;
    #pragma unroll
    for (int w = 0; w < 8; w++) { S += s1[w]; Q += s2[w]; }
    const float mean = S * (1.f / DD);
    const float var  = Q * (1.f / DD) - mean * mean;
    const float inv  = rsqrtf(var + LN_EPS);
    float4 gv = ((const float4*)g)[t];
    float4 bv = ((const float4*)b)[t];
    __half2 o01 = __floats2half2_rn((v.x - mean) * inv * gv.x + bv.x,
                                    (v.y - mean) * inv * gv.y + bv.y);
    __half2 o23 = __floats2half2_rn((v.z - mean) * inv * gv.z + bv.z,
                                    (v.w - mean) * inv * gv.w + bv.w);
    *(uint2*)(y + (size_t)row * DD + t * 4) =
        make_uint2(*(uint32_t*)&o01, *(uint32_t*)&o23);
}

// ---------------------------------------------------------------------------
// Tensor-core FP16 NT GEMM, cp.async double-buffered.
// C[M,N] = alpha*A[M,K]@B[N,K]^T (+bias)(relu)(+resid); fp32 and/or fp16 out.
// CTA 128x128, BK=32, 256 threads (8 warps, warp tile 64x32).
// ---------------------------------------------------------------------------
#define LDPH 40                      // halves per SMEM row (32 + 8 pad)
#define BUFB (128 * LDPH * 2)        // bytes per buffer = 10240

__global__ __launch_bounds__(256, 2)
void gemm_h_kernel(const __half* __restrict__ A, const __half* __restrict__ Bw,
                   float* __restrict__ C, __half* __restrict__ C16,
                   int M, int N, int K,
                   const float* __restrict__ bias, const float* __restrict__ resid,
                   float alpha, int relu) {
    __shared__ __align__(16) __half As[2][128][LDPH];
    __shared__ __align__(16) __half Bs[2][128][LDPH];

    const int tid  = threadIdx.x;
    const int warp = tid >> 5;
    const int lane = tid & 31;
    const int gid  = lane >> 2;
    const int tig  = lane & 3;
    const int wm = (warp >> 2) * 64;
    const int wn = (warp & 3) * 32;
    const int bm = blockIdx.y * 128;
    const int bn = blockIdx.x * 128;

    // staging: 128 rows x 4 x 16B groups per operand; 256 threads x 2 slots
    const int sr = tid >> 2;         // rows 0..63 (slot 0), +64 (slot 1)
    const int sg = tid & 3;          // 16B group in row

    const uint32_t sa0 = smem_u32(&As[0][sr][sg * 8]);
    const uint32_t sa1 = smem_u32(&As[0][sr + 64][sg * 8]);
    const uint32_t sb0 = smem_u32(&Bs[0][sr][sg * 8]);
    const uint32_t sb1 = smem_u32(&Bs[0][sr + 64][sg * 8]);

    // ldmatrix per-lane bases (buffer 0)
    const uint32_t a_base0 = smem_u32(&As[0][wm + (lane & 15)][(lane >> 4) * 8]);
    const uint32_t b_base0 =
        smem_u32(&Bs[0][wn + ((lane >> 4) << 3) + (lane & 7)][((lane >> 3) & 1) * 8]);

    float acc[4][4][4];
    #pragma unroll
    for (int mf = 0; mf < 4; mf++)
        #pragma unroll
        for (int nf = 0; nf < 4; nf++)
            #pragma unroll
            for (int u = 0; u < 4; u++) acc[mf][nf][u] = 0.f;

    const int nch = K >> 5;

    #define STAGE(c, buf) do {                                            \
        const int _k0 = (c) << 5;                                         \
        const uint32_t _off = (uint32_t)(buf) * BUFB;                     \
        CP16(sa0 + _off, A  + (size_t)(bm + sr) * K + _k0 + sg * 8);      \
        CP16(sa1 + _off, A  + (size_t)(bm + sr + 64) * K + _k0 + sg * 8); \
        CP16(sb0 + _off, Bw + (size_t)(bn + sr) * K + _k0 + sg * 8);      \
        CP16(sb1 + _off, Bw + (size_t)(bn + sr + 64) * K + _k0 + sg * 8); \
        CP_COMMIT();                                                      \
    } while (0)

    STAGE(0, 0);

    for (int c = 0; c < nch; c++) {
        const int buf = c & 1;
        if (c + 1 < nch) { STAGE(c + 1, buf ^ 1); CP_WAIT1(); }
        else             { CP_WAIT0(); }
        __syncthreads();

        const uint32_t aB = a_base0 + buf * BUFB;
        const uint32_t bB = b_base0 + buf * BUFB;
        #pragma unroll
        for (int ks = 0; ks < 2; ks++) {
            const uint32_t koff = (uint32_t)(ks * 16 * 2);
            uint32_t b[4][2];
            ldsm_x4(b[0][0], b[0][1], b[1][0], b[1][1], bB + koff);
            ldsm_x4(b[2][0], b[2][1], b[3][0], b[3][1],
                    bB + koff + 16 * LDPH * 2);
            #pragma unroll
            for (int mf = 0; mf < 4; mf++) {
                uint32_t a0, a1, a2, a3;
                ldsm_x4(a0, a1, a2, a3,
                        aB + koff + (uint32_t)(mf * 16 * LDPH * 2));
                #pragma unroll
                for (int nf = 0; nf < 4; nf++)
                    mma_f16(acc[mf][nf], a0, a1, a2, a3, b[nf][0], b[nf][1]);
            }
        }
        __syncthreads();
    }
    #undef STAGE

    // Epilogue
    #pragma unroll
    for (int mf = 0; mf < 4; mf++) {
        #pragma unroll
        for (int nf = 0; nf < 4; nf++) {
            const int cc = bn + wn + nf * 8 + 2 * tig;
            float bx = 0.f, by = 0.f;
            if (bias) { bx = bias[cc]; by = bias[cc + 1]; }
            #pragma unroll
            for (int h = 0; h < 2; h++) {
                const int row = bm + wm + mf * 16 + gid + h * 8;
                float v0 = acc[mf][nf][2 * h + 0] * alpha + bx;
                float v1 = acc[mf][nf][2 * h + 1] * alpha + by;
                if (relu) { v0 = fmaxf(v0, 0.f); v1 = fmaxf(v1, 0.f); }
                if (resid) {
                    float2 rr = *(const float2*)(resid + (size_t)row * N + cc);
                    v0 += rr.x; v1 += rr.y;
                }
                if (C) {
                    float2 ov = { v0, v1 };
                    *(float2*)(C + (size_t)row * N + cc) = ov;
                }
                if (C16) {
                    __half2 hv = __floats2half2_rn(v0, v1);
                    *(uint32_t*)(C16 + (size_t)row * N + cc) = *(uint32_t*)&hv;
                }
            }
        }
    }
}

// ---------------------------------------------------------------------------
// fp16 transpose (rows x cols) -> (cols x rows), 32x32 tiles
// ---------------------------------------------------------------------------
__global__ void transpose_h_kernel(const __half* __restrict__ in,
                                   __half* __restrict__ out, int R, int C) {
    __shared__ __half tile[32][34];
    const int c0 = blockIdx.x * 32;
    const int r0 = blockIdx.y * 32;
    for (int dy = threadIdx.y; dy < 32; dy += 8)
        tile[dy][threadIdx.x] = in[(size_t)(r0 + dy) * C + c0 + threadIdx.x];
    __syncthreads();
    for (int dy = threadIdx.y; dy < 32; dy += 8)
        out[(size_t)(c0 + dy) * R + r0 + threadIdx.x] = tile[threadIdx.x][dy];
}

// ---------------------------------------------------------------------------
// Softmax over the slots axis (i), per (b, j) column; in-place fp32, +EPS.
// ---------------------------------------------------------------------------
__global__ void colsoftmax_kernel(float* __restrict__ attn) {
    const int b = blockIdx.y;
    const int t = threadIdx.x;
    const int lane = t & 31;
    const int r = t >> 5;
    const int j = blockIdx.x * 32 + lane;
    float* base = attn + (size_t)b * NN * JJ;

    float m = -3.0e38f, s = 0.f;
    for (int i = r; i < NN; i += 4) {
        float x = base[(size_t)i * JJ + j];
        float nm = fmaxf(m, x);
        s = s * expf(m - nm) + expf(x - nm);
        m = nm;
    }
    __shared__ float sm[4][32], ss[4][32], gm[32], gs[32];
    sm[r][lane] = m;
    ss[r][lane] = s;
    __syncthreads();
    if (r == 0) {
        float M = sm[0][lane];
        #pragma unroll
        for (int p = 1; p < 4; p++) M = fmaxf(M, sm[p][lane]);
        float S = 0.f;
        #pragma unroll
        for (int p = 0; p < 4; p++) S += ss[p][lane] * expf(sm[p][lane] - M);
        gm[lane] = M;
        gs[lane] = 1.f / S;
    }
    __syncthreads();
    const float M = gm[lane], invS = gs[lane];
    for (int i = r; i < NN; i += 4) {
        size_t o = (size_t)i * JJ + j;
        base[o] = expf(base[o] - M) * invS + EPS;
    }
}

// ---------------------------------------------------------------------------
// Row renormalization over j, fp32 in -> fp16 out (separate buffer).
// ---------------------------------------------------------------------------
__global__ void rownorm_kernel(const float* __restrict__ attn,
                               __half* __restrict__ out) {
    const int row = blockIdx.x;
    const float* a = attn + (size_t)row * JJ;
    float s = 0.f;
    for (int i = threadIdx.x; i < JJ; i += 128) s += a[i];
    s = warp_sum(s);
    __shared__ float ws[4];
    if ((threadIdx.x & 31) == 0) ws[threadIdx.x >> 5] = s;
    __syncthreads();
    const float inv = 1.f / (ws[0] + ws[1] + ws[2] + ws[3]);
    __half* o = out + (size_t)row * JJ;
    for (int i = threadIdx.x; i < JJ; i += 128)
        o[i] = __float2half_rn(a[i] * inv);
}

// ---------------------------------------------------------------------------
// GRU cell elementwise (torch gate order r, z, n). In-place slots update.
// ---------------------------------------------------------------------------
__global__ void gru_kernel(const float* __restrict__ gi, const float* __restrict__ gh,
                           float* __restrict__ slots) {
    const int idx = blockIdx.x * blockDim.x + threadIdx.x;
    const int m = idx >> 10;
    const int d = idx & 1023;
    const size_t o = (size_t)m * (3 * DD) + d;
    const float r = 1.f / (1.f + expf(-(gi[o] + gh[o])));
    const float z = 1.f / (1.f + expf(-(gi[o + DD] + gh[o + DD])));
    const float n = tanhf(gi[o + 2 * DD] + r * gh[o + 2 * DD]);
    const float h = slots[idx];
    slots[idx] = (1.f - z) * n + z * h;
}

// ---------------------------------------------------------------------------
// Launch
// ---------------------------------------------------------------------------
static inline void gemm(const __half* A, const __half* B, float* C, __half* C16,
                        int M, int N, int K,
                        const float* bias, const float* resid, float alpha, int relu) {
    dim3 grid(N / 128, M / 128);
    gemm_h_kernel<<<grid, 256>>>(A, B, C, C16, M, N, K, bias, resid, alpha, relu);
}

static inline void f2h(const float* in, __half* out, int n) {
    f2h_kernel<<<(n / 4 + 255) / 256, 256>>>(in, out, n / 4);
}

extern "C" void kernel_launch(void* const* d_in, const int* in_sizes, int n_in,
                              void* d_out, int out_size) {
    const float* inputs = (const float*)d_in[0];
    const float* texts  = (const float*)d_in[1];
    const float* Wq   = (const float*)d_in[2];  const float* bq   = (const float*)d_in[3];
    const float* Wk   = (const float*)d_in[4];  const float* bk   = (const float*)d_in[5];
    const float* Wv   = (const float*)d_in[6];  const float* bv   = (const float*)d_in[7];
    const float* W_ih = (const float*)d_in[8];  const float* b_ih = (const float*)d_in[9];
    const float* W_hh = (const float*)d_in[10]; const float* b_hh = (const float*)d_in[11];
    const float* W1   = (const float*)d_in[12]; const float* b1   = (const float*)d_in[13];
    const float* W2   = (const float*)d_in[14]; const float* b2   = (const float*)d_in[15];
    const float* gin  = (const float*)d_in[16]; const float* bein = (const float*)d_in[17];
    const float* gsl  = (const float*)d_in[18]; const float* besl = (const float*)d_in[19];
    const float* gff  = (const float*)d_in[20]; const float* beff = (const float*)d_in[21];

    float *slots, *attn, *gi, *gh;
    __half *txn16, *k16, *v16, *vT16, *q16, *attn16, *upd16, *hid16, *lnb16, *slots16;
    __half *Wq16, *Wk16, *Wv16, *Wih16, *Whh16, *W116, *W216;
    cudaGetSymbolAddress((void**)&slots,  g_slots);
    cudaGetSymbolAddress((void**)&attn,   g_attn);
    cudaGetSymbolAddress((void**)&gi,     g_gi);
    cudaGetSymbolAddress((void**)&gh,     g_gh);
    cudaGetSymbolAddress((void**)&txn16,  g_txn16);
    cudaGetSymbolAddress((void**)&k16,    g_k16);
    cudaGetSymbolAddress((void**)&v16,    g_v16);
    cudaGetSymbolAddress((void**)&vT16,   g_vT16);
    cudaGetSymbolAddress((void**)&q16,    g_q16);
    cudaGetSymbolAddress((void**)&attn16, g_attn16);
    cudaGetSymbolAddress((void**)&upd16,  g_upd16);
    cudaGetSymbolAddress((void**)&hid16,  g_hid16);
    cudaGetSymbolAddress((void**)&lnb16,  g_lnb16);
    cudaGetSymbolAddress((void**)&slots16,g_slots16);
    cudaGetSymbolAddress((void**)&Wq16,   g_Wq16);
    cudaGetSymbolAddress((void**)&Wk16,   g_Wk16);
    cudaGetSymbolAddress((void**)&Wv16,   g_Wv16);
    cudaGetSymbolAddress((void**)&Wih16,  g_Wih16);
    cudaGetSymbolAddress((void**)&Whh16,  g_Whh16);
    cudaGetSymbolAddress((void**)&W116,   g_W116);
    cudaGetSymbolAddress((void**)&W216,   g_W216);

    // Weight + input conversions (once per launch; ~20us total)
    f2h(Wq, Wq16, DD * DD);
    f2h(Wk, Wk16, DD * DD);
    f2h(Wv, Wv16, DD * DD);
    f2h(W_ih, Wih16, 3 * DD * DD);
    f2h(W_hh, Whh16, 3 * DD * DD);
    f2h(W1, W116, HH * DD);
    f2h(W2, W216, DD * HH);
    f2h(inputs, slots16, MM * DD);

    // slots = inputs (fp32 master copy)
    cudaMemcpyAsync(slots, inputs, (size_t)MM * DD * sizeof(float),
                    cudaMemcpyDeviceToDevice);

    // texts_n = LN(texts); k/v = texts_n @ W^T + b (fp16); vT = v^T
    ln_kernel<<<JJ, 256>>>(texts, txn16, gin, bein);
    gemm(txn16, Wk16, 0, k16, JJ, DD, DD, bk, 0, 1.f, 0);
    gemm(txn16, Wv16, 0, v16, JJ, DD, DD, bv, 0, 1.f, 0);
    transpose_h_kernel<<<dim3(DD / 32, JJ / 32), dim3(32, 8)>>>(v16, vT16, JJ, DD);

    for (int it = 0; it < 3; it++) {
        // q = LN(slots) @ Wq^T + bq (fp16)
        ln_kernel<<<MM, 256>>>(slots, lnb16, gsl, besl);
        gemm(lnb16, Wq16, 0, q16, MM, DD, DD, bq, 0, 1.f, 0);

        // dots = q @ k^T * SCALE -> fp32
        gemm(q16, k16, attn, 0, MM, JJ, DD, 0, 0, SCALE, 0);

        // softmax over slots axis (+EPS), renormalize over j -> fp16
        colsoftmax_kernel<<<dim3(JJ / 32, BB), 128>>>(attn);
        rownorm_kernel<<<MM, 128>>>(attn, attn16);

        // updates = attn @ v (fp16)
        gemm(attn16, vT16, 0, upd16, MM, DD, JJ, 0, 0, 1.f, 0);

        // GRU gates (fp32 outputs for elementwise)
        gemm(upd16,   Wih16, gi, 0, MM, 3 * DD, DD, b_ih, 0, 1.f, 0);
        gemm(slots16, Whh16, gh, 0, MM, 3 * DD, DD, b_hh, 0, 1.f, 0);
        gru_kernel<<<(MM * DD) / 256, 256>>>(gi, gh, slots);

        // FF: slots += relu(LN(slots) @ W1^T + b1) @ W2^T + b2
        ln_kernel<<<MM, 256>>>(slots, lnb16, gff, beff);
        gemm(lnb16, W116, 0, hid16, MM, HH, DD, b1, 0, 1.f, 1);
        float* outp = (it == 2) ? (float*)d_out : slots;
        gemm(hid16, W216, outp, slots16, MM, DD, HH, b2, slots, 1.f, 0);
    }
}

// round 12
// speedup vs baseline: 6.1863x; 1.0301x over previous
#include <cuda_runtime.h>
#include <cuda_fp16.h>
#include <math.h>
#include <stdint.h>

// Problem constants
#define BB 64
#define NN 128
#define JJ 512
#define DD 1024
#define HH 4096
#define MM (BB * NN)          // 8192 rows
#define SCALE 0.03125f        // 1024^-0.5
#define EPS 1e-8f
#define LN_EPS 1e-5f

// ---------------------------------------------------------------------------
// Scratch (device globals; no allocations allowed)
// ---------------------------------------------------------------------------
__device__ float g_slots[MM * DD];
__device__ float g_attn [MM * JJ];

__device__ __align__(16) __half g_gi16  [MM * 3 * DD];
__device__ __align__(16) __half g_gh16  [MM * 3 * DD];
__device__ __align__(16) __half g_txn16 [JJ * DD];
__device__ __align__(16) __half g_k16   [JJ * DD];
__device__ __align__(16) __half g_v16   [JJ * DD];
__device__ __align__(16) __half g_vT16  [DD * JJ];
__device__ __align__(16) __half g_q16   [MM * DD];
__device__ __align__(16) __half g_attn16[MM * JJ];
__device__ __align__(16) __half g_upd16 [MM * DD];
__device__ __align__(16) __half g_hid16 [MM * HH];
__device__ __align__(16) __half g_lnb16 [MM * DD];
__device__ __align__(16) __half g_slots16[MM * DD];
__device__ __align__(16) __half g_Wq16  [DD * DD];
__device__ __align__(16) __half g_Wk16  [DD * DD];
__device__ __align__(16) __half g_Wv16  [DD * DD];
__device__ __align__(16) __half g_Wih16 [3 * DD * DD];
__device__ __align__(16) __half g_Whh16 [3 * DD * DD];
__device__ __align__(16) __half g_W116  [HH * DD];
__device__ __align__(16) __half g_W216  [DD * HH];

// ---------------------------------------------------------------------------
// Helpers
// ---------------------------------------------------------------------------
__device__ __forceinline__ float warp_sum(float v) {
    #pragma unroll
    for (int o = 16; o; o >>= 1) v += __shfl_xor_sync(0xFFFFFFFFu, v, o);
    return v;
}

__device__ __forceinline__ uint32_t smem_u32(const void* p) {
    uint32_t a;
    asm("{ .reg .u64 t; cvta.to.shared.u64 t, %1; cvt.u32.u64 %0, t; }"
        : "=r"(a) : "l"(p));
    return a;
}

// m16n8k16 fp16 MMA, fp32 accumulate (sm_80+ baseline)
__device__ __forceinline__ void mma_f16(float* c,
                                        uint32_t a0, uint32_t a1, uint32_t a2, uint32_t a3,
                                        uint32_t b0, uint32_t b1) {
    asm volatile(
        "mma.sync.aligned.m16n8k16.row.col.f32.f16.f16.f32 "
        "{%0,%1,%2,%3}, {%4,%5,%6,%7}, {%8,%9}, {%0,%1,%2,%3};"
        : "+f"(c[0]), "+f"(c[1]), "+f"(c[2]), "+f"(c[3])
        : "r"(a0), "r"(a1), "r"(a2), "r"(a3), "r"(b0), "r"(b1));
}

__device__ __forceinline__ void ldsm_x4(uint32_t& r0, uint32_t& r1,
                                        uint32_t& r2, uint32_t& r3, uint32_t addr) {
    asm volatile("ldmatrix.sync.aligned.m8n8.x4.shared.b16 {%0,%1,%2,%3}, [%4];"
                 : "=r"(r0), "=r"(r1), "=r"(r2), "=r"(r3) : "r"(addr));
}

#define CP16(smem, gptr) \
    asm volatile("cp.async.cg.shared.global [%0], [%1], 16;" \
                 :: "r"(smem), "l"(gptr))
#define CP_COMMIT() asm volatile("cp.async.commit_group;")
#define CP_WAIT2()  asm volatile("cp.async.wait_group 2;")
#define CP_WAIT1()  asm volatile("cp.async.wait_group 1;")
#define CP_WAIT0()  asm volatile("cp.async.wait_group 0;")

// ---------------------------------------------------------------------------
// fp32 -> fp16 conversion (n must be a multiple of 4)
// ---------------------------------------------------------------------------
__global__ void f2h_kernel(const float* __restrict__ in, __half* __restrict__ out,
                           int n4) {
    const int i = blockIdx.x * blockDim.x + threadIdx.x;
    if (i < n4) {
        float4 v = ((const float4*)in)[i];
        __half2 h01 = __floats2half2_rn(v.x, v.y);
        __half2 h23 = __floats2half2_rn(v.z, v.w);
        ((uint2*)out)[i] = make_uint2(*(uint32_t*)&h01, *(uint32_t*)&h23);
    }
}

// ---------------------------------------------------------------------------
// LayerNorm: fp32 in -> fp16 out. One block per row, D=1024, 256 threads.
// ---------------------------------------------------------------------------
__global__ void ln_kernel(const float* __restrict__ x, __half* __restrict__ y,
                          const float* __restrict__ g, const float* __restrict__ b) {
    const int row = blockIdx.x;
    const int t = threadIdx.x;
    const float4* xr = (const float4*)(x + (size_t)row * DD);
    float4 v = xr[t];
    float s = v.x + v.y + v.z + v.w;
    float q = v.x * v.x + v.y * v.y + v.z * v.z + v.w * v.w;
    s = warp_sum(s);
    q = warp_sum(q);
    __shared__ float s1[8], s2[8];
    if ((t & 31) == 0) { s1[t >> 5] = s; s2[t >> 5] = q; }
    __syncthreads();
    float S = 0.f, Q = 0.f;
    #pragma unroll
    for (int w = 0; w < 8; w++) { S += s1[w]; Q += s2[w]; }
    const float mean = S * (1.f / DD);
    const float var  = Q * (1.f / DD) - mean * mean;
    const float inv  = rsqrtf(var + LN_EPS);
    float4 gv = ((const float4*)g)[t];
    float4 bv = ((const float4*)b)[t];
    __half2 o01 = __floats2half2_rn((v.x - mean) * inv * gv.x + bv.x,
                                    (v.y - mean) * inv * gv.y + bv.y);
    __half2 o23 = __floats2half2_rn((v.z - mean) * inv * gv.z + bv.z,
                                    (v.w - mean) * inv * gv.w + bv.w);
    *(uint2*)(y + (size_t)row * DD + t * 4) =
        make_uint2(*(uint32_t*)&o01, *(uint32_t*)&o23);
}

// ---------------------------------------------------------------------------
// Tensor-core FP16 NT GEMM, 3-stage cp.async pipeline (dynamic SMEM).
// C[M,N] = alpha*A[M,K]@B[N,K]^T (+bias)(relu)(+resid); fp32 and/or fp16 out.
// CTA 128x128, BK=32, 256 threads (8 warps, warp tile 64x32).
// ---------------------------------------------------------------------------
#define LDPH 40                       // halves per SMEM row (32 + 8 pad)
#define ROWB (LDPH * 2)               // 80 bytes per row
#define HALFBUF (128 * ROWB)          // 10240 bytes (one operand tile)
#define SBUF (2 * HALFBUF)            // 20480 bytes per stage (A + B)
#define SMEM_DYN (3 * SBUF)           // 61440 bytes

__global__ __launch_bounds__(256, 2)
void gemm_h_kernel(const __half* __restrict__ A, const __half* __restrict__ Bw,
                   float* __restrict__ C, __half* __restrict__ C16,
                   int M, int N, int K,
                   const float* __restrict__ bias, const float* __restrict__ resid,
                   float alpha, int relu) {
    extern __shared__ __align__(16) char smem_raw[];
    const uint32_t sbase = smem_u32(smem_raw);

    const int tid  = threadIdx.x;
    const int warp = tid >> 5;
    const int lane = tid & 31;
    const int gid  = lane >> 2;
    const int tig  = lane & 3;
    const int wm = (warp >> 2) * 64;
    const int wn = (warp & 3) * 32;
    const int bm = blockIdx.y * 128;
    const int bn = blockIdx.x * 128;

    // staging: 128 rows x 4 x 16B groups per operand; 256 threads x 2 slots
    const int sr = tid >> 2;          // rows 0..63 (slot 0), +64 (slot 1)
    const int sg = tid & 3;           // 16B group in row

    const uint32_t sa0 = sbase + (uint32_t)(sr * ROWB + sg * 16);
    const uint32_t sa1 = sa0 + 64 * ROWB;
    const uint32_t sb0 = sa0 + HALFBUF;
    const uint32_t sb1 = sa1 + HALFBUF;

    // ldmatrix per-lane bases (stage 0)
    const uint32_t a_base0 = sbase +
        (uint32_t)((wm + (lane & 15)) * ROWB + (lane >> 4) * 16);
    const uint32_t b_base0 = sbase + HALFBUF +
        (uint32_t)((wn + ((lane >> 4) << 3) + (lane & 7)) * ROWB +
                   ((lane >> 3) & 1) * 16);

    float acc[4][4][4];
    #pragma unroll
    for (int mf = 0; mf < 4; mf++)
        #pragma unroll
        for (int nf = 0; nf < 4; nf++)
            #pragma unroll
            for (int u = 0; u < 4; u++) acc[mf][nf][u] = 0.f;

    const int nch = K >> 5;

    #define STAGE(c, buf) do {                                            \
        const int _k0 = (c) << 5;                                         \
        const uint32_t _off = (uint32_t)(buf) * SBUF;                     \
        CP16(sa0 + _off, A  + (size_t)(bm + sr) * K + _k0 + sg * 8);      \
        CP16(sa1 + _off, A  + (size_t)(bm + sr + 64) * K + _k0 + sg * 8); \
        CP16(sb0 + _off, Bw + (size_t)(bn + sr) * K + _k0 + sg * 8);      \
        CP16(sb1 + _off, Bw + (size_t)(bn + sr + 64) * K + _k0 + sg * 8); \
        CP_COMMIT();                                                      \
    } while (0)

    STAGE(0, 0);
    if (nch > 1) STAGE(1, 1);

    int buf = 0;
    for (int c = 0; c < nch; c++) {
        const int ahead = nch - 1 - c;          // chunks not yet computed after c
        if (ahead >= 2) STAGE(c + 2, (buf + 2 >= 3) ? buf - 1 : buf + 2);
        if (ahead >= 2)      { CP_WAIT2(); }
        else if (ahead == 1) { CP_WAIT1(); }
        else                 { CP_WAIT0(); }
        __syncthreads();

        const uint32_t aB = a_base0 + (uint32_t)buf * SBUF;
        const uint32_t bB = b_base0 + (uint32_t)buf * SBUF;
        #pragma unroll
        for (int ks = 0; ks < 2; ks++) {
            const uint32_t koff = (uint32_t)(ks * 16 * 2);
            uint32_t b[4][2];
            ldsm_x4(b[0][0], b[0][1], b[1][0], b[1][1], bB + koff);
            ldsm_x4(b[2][0], b[2][1], b[3][0], b[3][1],
                    bB + koff + 16 * ROWB);
            #pragma unroll
            for (int mf = 0; mf < 4; mf++) {
                uint32_t a0, a1, a2, a3;
                ldsm_x4(a0, a1, a2, a3,
                        aB + koff + (uint32_t)(mf * 16 * ROWB));
                #pragma unroll
                for (int nf = 0; nf < 4; nf++)
                    mma_f16(acc[mf][nf], a0, a1, a2, a3, b[nf][0], b[nf][1]);
            }
        }
        __syncthreads();
        buf = (buf + 1 >= 3) ? 0 : buf + 1;
    }
    #undef STAGE

    // Epilogue
    #pragma unroll
    for (int mf = 0; mf < 4; mf++) {
        #pragma unroll
        for (int nf = 0; nf < 4; nf++) {
            const int cc = bn + wn + nf * 8 + 2 * tig;
            float bx = 0.f, by = 0.f;
            if (bias) { bx = bias[cc]; by = bias[cc + 1]; }
            #pragma unroll
            for (int h = 0; h < 2; h++) {
                const int row = bm + wm + mf * 16 + gid + h * 8;
                float v0 = acc[mf][nf][2 * h + 0] * alpha + bx;
                float v1 = acc[mf][nf][2 * h + 1] * alpha + by;
                if (relu) { v0 = fmaxf(v0, 0.f); v1 = fmaxf(v1, 0.f); }
                if (resid) {
                    float2 rr = *(const float2*)(resid + (size_t)row * N + cc);
                    v0 += rr.x; v1 += rr.y;
                }
                if (C) {
                    float2 ov = { v0, v1 };
                    *(float2*)(C + (size_t)row * N + cc) = ov;
                }
                if (C16) {
                    __half2 hv = __floats2half2_rn(v0, v1);
                    *(uint32_t*)(C16 + (size_t)row * N + cc) = *(uint32_t*)&hv;
                }
            }
        }
    }
}

// ---------------------------------------------------------------------------
// fp16 transpose (rows x cols) -> (cols x rows), 32x32 tiles
// ---------------------------------------------------------------------------
__global__ void transpose_h_kernel(const __half* __restrict__ in,
                                   __half* __restrict__ out, int R, int C) {
    __shared__ __half tile[32][34];
    const int c0 = blockIdx.x * 32;
    const int r0 = blockIdx.y * 32;
    for (int dy = threadIdx.y; dy < 32; dy += 8)
        tile[dy][threadIdx.x] = in[(size_t)(r0 + dy) * C + c0 + threadIdx.x];
    __syncthreads();
    for (int dy = threadIdx.y; dy < 32; dy += 8)
        out[(size_t)(c0 + dy) * R + r0 + threadIdx.x] = tile[threadIdx.x][dy];
}

// ---------------------------------------------------------------------------
// Softmax over the slots axis (i), per (b, j) column; in-place fp32, +EPS.
// ---------------------------------------------------------------------------
__global__ void colsoftmax_kernel(float* __restrict__ attn) {
    const int b = blockIdx.y;
    const int t = threadIdx.x;
    const int lane = t & 31;
    const int r = t >> 5;
    const int j = blockIdx.x * 32 + lane;
    float* base = attn + (size_t)b * NN * JJ;

    float m = -3.0e38f, s = 0.f;
    for (int i = r; i < NN; i += 4) {
        float x = base[(size_t)i * JJ + j];
        float nm = fmaxf(m, x);
        s = s * expf(m - nm) + expf(x - nm);
        m = nm;
    }
    __shared__ float sm[4][32], ss[4][32], gm[32], gs[32];
    sm[r][lane] = m;
    ss[r][lane] = s;
    __syncthreads();
    if (r == 0) {
        float M = sm[0][lane];
        #pragma unroll
        for (int p = 1; p < 4; p++) M = fmaxf(M, sm[p][lane]);
        float S = 0.f;
        #pragma unroll
        for (int p = 0; p < 4; p++) S += ss[p][lane] * expf(sm[p][lane] - M);
        gm[lane] = M;
        gs[lane] = 1.f / S;
    }
    __syncthreads();
    const float M = gm[lane], invS = gs[lane];
    for (int i = r; i < NN; i += 4) {
        size_t o = (size_t)i * JJ + j;
        base[o] = expf(base[o] - M) * invS + EPS;
    }
}

// ---------------------------------------------------------------------------
// Row renormalization over j, fp32 in -> fp16 out (separate buffer).
// ---------------------------------------------------------------------------
__global__ void rownorm_kernel(const float* __restrict__ attn,
                               __half* __restrict__ out) {
    const int row = blockIdx.x;
    const float* a = attn + (size_t)row * JJ;
    float s = 0.f;
    for (int i = threadIdx.x; i < JJ; i += 128) s += a[i];
    s = warp_sum(s);
    __shared__ float ws[4];
    if ((threadIdx.x & 31) == 0) ws[threadIdx.x >> 5] = s;
    __syncthreads();
    const float inv = 1.f / (ws[0] + ws[1] + ws[2] + ws[3]);
    __half* o = out + (size_t)row * JJ;
    for (int i = threadIdx.x; i < JJ; i += 128)
        o[i] = __float2half_rn(a[i] * inv);
}

// ---------------------------------------------------------------------------
// GRU cell elementwise (torch gate order r, z, n), fp16 gates. In-place slots.
// ---------------------------------------------------------------------------
__global__ void gru_kernel(const __half* __restrict__ gi, const __half* __restrict__ gh,
                           float* __restrict__ slots) {
    const int idx = blockIdx.x * blockDim.x + threadIdx.x;
    const int m = idx >> 10;
    const int d = idx & 1023;
    const size_t o = (size_t)m * (3 * DD) + d;
    const float ir = __half2float(gi[o]),          hr = __half2float(gh[o]);
    const float iz = __half2float(gi[o + DD]),     hz = __half2float(gh[o + DD]);
    const float in_ = __half2float(gi[o + 2 * DD]), hn = __half2float(gh[o + 2 * DD]);
    const float r = 1.f / (1.f + expf(-(ir + hr)));
    const float z = 1.f / (1.f + expf(-(iz + hz)));
    const float n = tanhf(in_ + r * hn);
    const float h = slots[idx];
    slots[idx] = (1.f - z) * n + z * h;
}

// ---------------------------------------------------------------------------
// Launch
// ---------------------------------------------------------------------------
static inline void gemm(const __half* A, const __half* B, float* C, __half* C16,
                        int M, int N, int K,
                        const float* bias, const float* resid, float alpha, int relu) {
    dim3 grid(N / 128, M / 128);
    gemm_h_kernel<<<grid, 256, SMEM_DYN>>>(A, B, C, C16, M, N, K, bias, resid,
                                           alpha, relu);
}

static inline void f2h(const float* in, __half* out, int n) {
    f2h_kernel<<<(n / 4 + 255) / 256, 256>>>(in, out, n / 4);
}

extern "C" void kernel_launch(void* const* d_in, const int* in_sizes, int n_in,
                              void* d_out, int out_size) {
    const float* inputs = (const float*)d_in[0];
    const float* texts  = (const float*)d_in[1];
    const float* Wq   = (const float*)d_in[2];  const float* bq   = (const float*)d_in[3];
    const float* Wk   = (const float*)d_in[4];  const float* bk   = (const float*)d_in[5];
    const float* Wv   = (const float*)d_in[6];  const float* bv   = (const float*)d_in[7];
    const float* W_ih = (const float*)d_in[8];  const float* b_ih = (const float*)d_in[9];
    const float* W_hh = (const float*)d_in[10]; const float* b_hh = (const float*)d_in[11];
    const float* W1   = (const float*)d_in[12]; const float* b1   = (const float*)d_in[13];
    const float* W2   = (const float*)d_in[14]; const float* b2   = (const float*)d_in[15];
    const float* gin  = (const float*)d_in[16]; const float* bein = (const float*)d_in[17];
    const float* gsl  = (const float*)d_in[18]; const float* besl = (const float*)d_in[19];
    const float* gff  = (const float*)d_in[20]; const float* beff = (const float*)d_in[21];

    cudaFuncSetAttribute(gemm_h_kernel, cudaFuncAttributeMaxDynamicSharedMemorySize,
                         SMEM_DYN);

    float *slots, *attn;
    __half *gi16, *gh16;
    __half *txn16, *k16, *v16, *vT16, *q16, *attn16, *upd16, *hid16, *lnb16, *slots16;
    __half *Wq16, *Wk16, *Wv16, *Wih16, *Whh16, *W116, *W216;
    cudaGetSymbolAddress((void**)&slots,  g_slots);
    cudaGetSymbolAddress((void**)&attn,   g_attn);
    cudaGetSymbolAddress((void**)&gi16,   g_gi16);
    cudaGetSymbolAddress((void**)&gh16,   g_gh16);
    cudaGetSymbolAddress((void**)&txn16,  g_txn16);
    cudaGetSymbolAddress((void**)&k16,    g_k16);
    cudaGetSymbolAddress((void**)&v16,    g_v16);
    cudaGetSymbolAddress((void**)&vT16,   g_vT16);
    cudaGetSymbolAddress((void**)&q16,    g_q16);
    cudaGetSymbolAddress((void**)&attn16, g_attn16);
    cudaGetSymbolAddress((void**)&upd16,  g_upd16);
    cudaGetSymbolAddress((void**)&hid16,  g_hid16);
    cudaGetSymbolAddress((void**)&lnb16,  g_lnb16);
    cudaGetSymbolAddress((void**)&slots16,g_slots16);
    cudaGetSymbolAddress((void**)&Wq16,   g_Wq16);
    cudaGetSymbolAddress((void**)&Wk16,   g_Wk16);
    cudaGetSymbolAddress((void**)&Wv16,   g_Wv16);
    cudaGetSymbolAddress((void**)&Wih16,  g_Wih16);
    cudaGetSymbolAddress((void**)&Whh16,  g_Whh16);
    cudaGetSymbolAddress((void**)&W116,   g_W116);
    cudaGetSymbolAddress((void**)&W216,   g_W216);

    // Weight + input conversions (once per launch; ~25us total)
    f2h(Wq, Wq16, DD * DD);
    f2h(Wk, Wk16, DD * DD);
    f2h(Wv, Wv16, DD * DD);
    f2h(W_ih, Wih16, 3 * DD * DD);
    f2h(W_hh, Whh16, 3 * DD * DD);
    f2h(W1, W116, HH * DD);
    f2h(W2, W216, DD * HH);
    f2h(inputs, slots16, MM * DD);

    // slots = inputs (fp32 master copy)
    cudaMemcpyAsync(slots, inputs, (size_t)MM * DD * sizeof(float),
                    cudaMemcpyDeviceToDevice);

    // texts_n = LN(texts); k/v = texts_n @ W^T + b (fp16); vT = v^T
    ln_kernel<<<JJ, 256>>>(texts, txn16, gin, bein);
    gemm(txn16, Wk16, 0, k16, JJ, DD, DD, bk, 0, 1.f, 0);
    gemm(txn16, Wv16, 0, v16, JJ, DD, DD, bv, 0, 1.f, 0);
    transpose_h_kernel<<<dim3(DD / 32, JJ / 32), dim3(32, 8)>>>(v16, vT16, JJ, DD);

    for (int it = 0; it < 3; it++) {
        // q = LN(slots) @ Wq^T + bq (fp16)
        ln_kernel<<<MM, 256>>>(slots, lnb16, gsl, besl);
        gemm(lnb16, Wq16, 0, q16, MM, DD, DD, bq, 0, 1.f, 0);

        // dots = q @ k^T * SCALE -> fp32
        gemm(q16, k16, attn, 0, MM, JJ, DD, 0, 0, SCALE, 0);

        // softmax over slots axis (+EPS), renormalize over j -> fp16
        colsoftmax_kernel<<<dim3(JJ / 32, BB), 128>>>(attn);
        rownorm_kernel<<<MM, 128>>>(attn, attn16);

        // updates = attn @ v (fp16)
        gemm(attn16, vT16, 0, upd16, MM, DD, JJ, 0, 0, 1.f, 0);

        // GRU gates (fp16 outputs; bias added fp32 in epilogue then rounded)
        gemm(upd16,   Wih16, 0, gi16, MM, 3 * DD, DD, b_ih, 0, 1.f, 0);
        gemm(slots16, Whh16, 0, gh16, MM, 3 * DD, DD, b_hh, 0, 1.f, 0);
        gru_kernel<<<(MM * DD) / 256, 256>>>(gi16, gh16, slots);

        // FF: slots += relu(LN(slots) @ W1^T + b1) @ W2^T + b2
        ln_kernel<<<MM, 256>>>(slots, lnb16, gff, beff);
        gemm(lnb16, W116, 0, hid16, MM, HH, DD, b1, 0, 1.f, 1);
        float* outp = (it == 2) ? (float*)d_out : slots;
        gemm(hid16, W216, outp, slots16, MM, DD, HH, b2, slots, 1.f, 0);
    }
}

// round 13
// speedup vs baseline: 6.3742x; 1.0304x over previous
#include <cuda_runtime.h>
#include <cuda_fp16.h>
#include <math.h>
#include <stdint.h>

// Problem constants
#define BB 64
#define NN 128
#define JJ 512
#define DD 1024
#define HH 4096
#define MM (BB * NN)          // 8192 rows
#define SCALE 0.03125f        // 1024^-0.5
#define EPS 1e-8f
#define LN_EPS 1e-5f

// ---------------------------------------------------------------------------
// Scratch (device globals; no allocations allowed)
// ---------------------------------------------------------------------------
__device__ float g_slots[MM * DD];
__device__ float g_attn [MM * JJ];

__device__ __align__(16) __half g_gi16  [MM * 3 * DD];
__device__ __align__(16) __half g_gh16  [MM * 3 * DD];
__device__ __align__(16) __half g_txn16 [JJ * DD];
__device__ __align__(16) __half g_k16   [JJ * DD];
__device__ __align__(16) __half g_v16   [JJ * DD];
__device__ __align__(16) __half g_vT16  [DD * JJ];
__device__ __align__(16) __half g_q16   [MM * DD];
__device__ __align__(16) __half g_attn16[MM * JJ];
__device__ __align__(16) __half g_upd16 [MM * DD];
__device__ __align__(16) __half g_hid16 [MM * HH];
__device__ __align__(16) __half g_lnb16 [MM * DD];
__device__ __align__(16) __half g_slots16[MM * DD];
__device__ __align__(16) __half g_Wq16  [DD * DD];
__device__ __align__(16) __half g_Wk16  [DD * DD];
__device__ __align__(16) __half g_Wv16  [DD * DD];
__device__ __align__(16) __half g_Wih16 [3 * DD * DD];
__device__ __align__(16) __half g_Whh16 [3 * DD * DD];
__device__ __align__(16) __half g_W116  [HH * DD];
__device__ __align__(16) __half g_W216  [DD * HH];

// ---------------------------------------------------------------------------
// Helpers
// ---------------------------------------------------------------------------
__device__ __forceinline__ float warp_sum(float v) {
    #pragma unroll
    for (int o = 16; o; o >>= 1) v += __shfl_xor_sync(0xFFFFFFFFu, v, o);
    return v;
}

__device__ __forceinline__ uint32_t smem_u32(const void* p) {
    uint32_t a;
    asm("{ .reg .u64 t; cvta.to.shared.u64 t, %1; cvt.u32.u64 %0, t; }"
        : "=r"(a) : "l"(p));
    return a;
}

__device__ __forceinline__ float tanh_fast(float x) {
    float y;
    asm("tanh.approx.f32 %0, %1;" : "=f"(y) : "f"(x));
    return y;
}
__device__ __forceinline__ float sigm_fast(float x) {
    return 1.f / (1.f + __expf(-x));
}

// m16n8k16 fp16 MMA, fp32 accumulate (sm_80+ baseline)
__device__ __forceinline__ void mma_f16(float* c,
                                        uint32_t a0, uint32_t a1, uint32_t a2, uint32_t a3,
                                        uint32_t b0, uint32_t b1) {
    asm volatile(
        "mma.sync.aligned.m16n8k16.row.col.f32.f16.f16.f32 "
        "{%0,%1,%2,%3}, {%4,%5,%6,%7}, {%8,%9}, {%0,%1,%2,%3};"
        : "+f"(c[0]), "+f"(c[1]), "+f"(c[2]), "+f"(c[3])
        : "r"(a0), "r"(a1), "r"(a2), "r"(a3), "r"(b0), "r"(b1));
}

__device__ __forceinline__ void ldsm_x4(uint32_t& r0, uint32_t& r1,
                                        uint32_t& r2, uint32_t& r3, uint32_t addr) {
    asm volatile("ldmatrix.sync.aligned.m8n8.x4.shared.b16 {%0,%1,%2,%3}, [%4];"
                 : "=r"(r0), "=r"(r1), "=r"(r2), "=r"(r3) : "r"(addr));
}

#define CP16(smem, gptr) \
    asm volatile("cp.async.cg.shared.global [%0], [%1], 16;" \
                 :: "r"(smem), "l"(gptr))
#define CP_COMMIT() asm volatile("cp.async.commit_group;")
#define CP_WAIT2()  asm volatile("cp.async.wait_group 2;")
#define CP_WAIT1()  asm volatile("cp.async.wait_group 1;")
#define CP_WAIT0()  asm volatile("cp.async.wait_group 0;")

// ---------------------------------------------------------------------------
// fp32 -> fp16 conversion (n must be a multiple of 4)
// ---------------------------------------------------------------------------
__global__ void f2h_kernel(const float* __restrict__ in, __half* __restrict__ out,
                           int n4) {
    const int i = blockIdx.x * blockDim.x + threadIdx.x;
    if (i < n4) {
        float4 v = ((const float4*)in)[i];
        __half2 h01 = __floats2half2_rn(v.x, v.y);
        __half2 h23 = __floats2half2_rn(v.z, v.w);
        ((uint2*)out)[i] = make_uint2(*(uint32_t*)&h01, *(uint32_t*)&h23);
    }
}

// ---------------------------------------------------------------------------
// LayerNorm: fp32 in -> fp16 out. One block per row, D=1024, 256 threads.
// ---------------------------------------------------------------------------
__global__ void ln_kernel(const float* __restrict__ x, __half* __restrict__ y,
                          const float* __restrict__ g, const float* __restrict__ b) {
    const int row = blockIdx.x;
    const int t = threadIdx.x;
    const float4* xr = (const float4*)(x + (size_t)row * DD);
    float4 v = xr[t];
    float s = v.x + v.y + v.z + v.w;
    float q = v.x * v.x + v.y * v.y + v.z * v.z + v.w * v.w;
    s = warp_sum(s);
    q = warp_sum(q);
    __shared__ float s1[8], s2[8];
    if ((t & 31) == 0) { s1[t >> 5] = s; s2[t >> 5] = q; }
    __syncthreads();
    float S = 0.f, Q = 0.f;
    #pragma unroll
    for (int w = 0; w < 8; w++) { S += s1[w]; Q += s2[w]; }
    const float mean = S * (1.f / DD);
    const float var  = Q * (1.f / DD) - mean * mean;
    const float inv  = rsqrtf(var + LN_EPS);
    float4 gv = ((const float4*)g)[t];
    float4 bv = ((const float4*)b)[t];
    __half2 o01 = __floats2half2_rn((v.x - mean) * inv * gv.x + bv.x,
                                    (v.y - mean) * inv * gv.y + bv.y);
    __half2 o23 = __floats2half2_rn((v.z - mean) * inv * gv.z + bv.z,
                                    (v.w - mean) * inv * gv.w + bv.w);
    *(uint2*)(y + (size_t)row * DD + t * 4) =
        make_uint2(*(uint32_t*)&o01, *(uint32_t*)&o23);
}

// ---------------------------------------------------------------------------
// Tensor-core FP16 NT GEMM, 3-stage cp.async pipeline (dynamic SMEM).
// C[M,N] = alpha*A[M,K]@B[N,K]^T (+bias)(relu)(+resid); fp32 and/or fp16 out.
// CTA 128x128, BK=32, 256 threads (8 warps, warp tile 64x32).
// ---------------------------------------------------------------------------
#define LDPH 40                       // halves per SMEM row (32 + 8 pad)
#define ROWB (LDPH * 2)               // 80 bytes per row
#define HALFBUF (128 * ROWB)          // 10240 bytes (one operand tile)
#define SBUF (2 * HALFBUF)            // 20480 bytes per stage (A + B)
#define SMEM_DYN (3 * SBUF)           // 61440 bytes

__global__ __launch_bounds__(256, 2)
void gemm_h_kernel(const __half* __restrict__ A, const __half* __restrict__ Bw,
                   float* __restrict__ C, __half* __restrict__ C16,
                   int M, int N, int K,
                   const float* __restrict__ bias, const float* __restrict__ resid,
                   float alpha, int relu) {
    extern __shared__ __align__(16) char smem_raw[];
    const uint32_t sbase = smem_u32(smem_raw);

    const int tid  = threadIdx.x;
    const int warp = tid >> 5;
    const int lane = tid & 31;
    const int gid  = lane >> 2;
    const int tig  = lane & 3;
    const int wm = (warp >> 2) * 64;
    const int wn = (warp & 3) * 32;
    const int bm = blockIdx.y * 128;
    const int bn = blockIdx.x * 128;

    const int sr = tid >> 2;          // staging rows 0..63 (slot 0), +64
    const int sg = tid & 3;           // 16B group in row

    const uint32_t sa0 = sbase + (uint32_t)(sr * ROWB + sg * 16);
    const uint32_t sa1 = sa0 + 64 * ROWB;
    const uint32_t sb0 = sa0 + HALFBUF;
    const uint32_t sb1 = sa1 + HALFBUF;

    const uint32_t a_base0 = sbase +
        (uint32_t)((wm + (lane & 15)) * ROWB + (lane >> 4) * 16);
    const uint32_t b_base0 = sbase + HALFBUF +
        (uint32_t)((wn + ((lane >> 4) << 3) + (lane & 7)) * ROWB +
                   ((lane >> 3) & 1) * 16);

    float acc[4][4][4];
    #pragma unroll
    for (int mf = 0; mf < 4; mf++)
        #pragma unroll
        for (int nf = 0; nf < 4; nf++)
            #pragma unroll
            for (int u = 0; u < 4; u++) acc[mf][nf][u] = 0.f;

    const int nch = K >> 5;

    #define STAGE(c, buf) do {                                            \
        const int _k0 = (c) << 5;                                         \
        const uint32_t _off = (uint32_t)(buf) * SBUF;                     \
        CP16(sa0 + _off, A  + (size_t)(bm + sr) * K + _k0 + sg * 8);      \
        CP16(sa1 + _off, A  + (size_t)(bm + sr + 64) * K + _k0 + sg * 8); \
        CP16(sb0 + _off, Bw + (size_t)(bn + sr) * K + _k0 + sg * 8);      \
        CP16(sb1 + _off, Bw + (size_t)(bn + sr + 64) * K + _k0 + sg * 8); \
        CP_COMMIT();                                                      \
    } while (0)

    STAGE(0, 0);
    if (nch > 1) STAGE(1, 1);

    int buf = 0;
    for (int c = 0; c < nch; c++) {
        const int ahead = nch - 1 - c;
        if (ahead >= 2) STAGE(c + 2, (buf + 2 >= 3) ? buf - 1 : buf + 2);
        if (ahead >= 2)      { CP_WAIT2(); }
        else if (ahead == 1) { CP_WAIT1(); }
        else                 { CP_WAIT0(); }
        __syncthreads();

        const uint32_t aB = a_base0 + (uint32_t)buf * SBUF;
        const uint32_t bB = b_base0 + (uint32_t)buf * SBUF;
        #pragma unroll
        for (int ks = 0; ks < 2; ks++) {
            const uint32_t koff = (uint32_t)(ks * 16 * 2);
            uint32_t b[4][2];
            ldsm_x4(b[0][0], b[0][1], b[1][0], b[1][1], bB + koff);
            ldsm_x4(b[2][0], b[2][1], b[3][0], b[3][1],
                    bB + koff + 16 * ROWB);
            #pragma unroll
            for (int mf = 0; mf < 4; mf++) {
                uint32_t a0, a1, a2, a3;
                ldsm_x4(a0, a1, a2, a3,
                        aB + koff + (uint32_t)(mf * 16 * ROWB));
                #pragma unroll
                for (int nf = 0; nf < 4; nf++)
                    mma_f16(acc[mf][nf], a0, a1, a2, a3, b[nf][0], b[nf][1]);
            }
        }
        __syncthreads();
        buf = (buf + 1 >= 3) ? 0 : buf + 1;
    }
    #undef STAGE

    // Epilogue
    #pragma unroll
    for (int mf = 0; mf < 4; mf++) {
        #pragma unroll
        for (int nf = 0; nf < 4; nf++) {
            const int cc = bn + wn + nf * 8 + 2 * tig;
            float bx = 0.f, by = 0.f;
            if (bias) { bx = bias[cc]; by = bias[cc + 1]; }
            #pragma unroll
            for (int h = 0; h < 2; h++) {
                const int row = bm + wm + mf * 16 + gid + h * 8;
                float v0 = acc[mf][nf][2 * h + 0] * alpha + bx;
                float v1 = acc[mf][nf][2 * h + 1] * alpha + by;
                if (relu) { v0 = fmaxf(v0, 0.f); v1 = fmaxf(v1, 0.f); }
                if (resid) {
                    float2 rr = *(const float2*)(resid + (size_t)row * N + cc);
                    v0 += rr.x; v1 += rr.y;
                }
                if (C) {
                    float2 ov = { v0, v1 };
                    *(float2*)(C + (size_t)row * N + cc) = ov;
                }
                if (C16) {
                    __half2 hv = __floats2half2_rn(v0, v1);
                    *(uint32_t*)(C16 + (size_t)row * N + cc) = *(uint32_t*)&hv;
                }
            }
        }
    }
}

// ---------------------------------------------------------------------------
// fp16 transpose (rows x cols) -> (cols x rows), 32x32 tiles
// ---------------------------------------------------------------------------
__global__ void transpose_h_kernel(const __half* __restrict__ in,
                                   __half* __restrict__ out, int R, int C) {
    __shared__ __half tile[32][34];
    const int c0 = blockIdx.x * 32;
    const int r0 = blockIdx.y * 32;
    for (int dy = threadIdx.y; dy < 32; dy += 8)
        tile[dy][threadIdx.x] = in[(size_t)(r0 + dy) * C + c0 + threadIdx.x];
    __syncthreads();
    for (int dy = threadIdx.y; dy < 32; dy += 8)
        out[(size_t)(c0 + dy) * R + r0 + threadIdx.x] = tile[threadIdx.x][dy];
}

// ---------------------------------------------------------------------------
// Fused softmax: per batch b, softmax over slots axis (i) per column j,
// +EPS, then renormalize over j, write fp16. One CTA per b, 512 threads.
// Dynamic SMEM holds the 128x512 exp tile in fp16 (131072 B).
// ---------------------------------------------------------------------------
#define SMEM_SOFTMAX (NN * JJ * 2)

__global__ void softmax_fused_kernel(const float* __restrict__ attn,
                                     __half* __restrict__ out) {
    extern __shared__ __half sh[];            // [NN][JJ] unnormalized exp
    __shared__ float cinv[JJ];
    __shared__ float rinv[NN];
    const int b = blockIdx.x;
    const int j = threadIdx.x;                // 0..511
    const float* base = attn + (size_t)b * NN * JJ;

    // pass A: column max over i (no exp)
    float m = -3.0e38f;
    for (int i = 0; i < NN; i++)
        m = fmaxf(m, base[(size_t)i * JJ + j]);

    // pass B: one exp per element, store to smem, accumulate column sum
    float s = 0.f;
    for (int i = 0; i < NN; i++) {
        float e = __expf(base[(size_t)i * JJ + j] - m);
        s += e;
        sh[i * JJ + j] = __float2half_rn(e);
    }
    cinv[j] = 1.f / s;
    __syncthreads();

    // row sums of (e * cinv_j) + JJ*EPS
    const int warp = j >> 5, lane = j & 31;
    for (int r = warp * 8; r < warp * 8 + 8; r++) {
        float s2 = 0.f;
        for (int c = lane; c < JJ; c += 32)
            s2 += __half2float(sh[r * JJ + c]) * cinv[c];
        s2 = warp_sum(s2);
        if (lane == 0) rinv[r] = 1.f / (s2 + (float)JJ * EPS);
    }
    __syncthreads();

    // write normalized fp16
    __half* o = out + (size_t)b * NN * JJ;
    const float ci = cinv[j];
    for (int i = 0; i < NN; i++) {
        float v = (__half2float(sh[i * JJ + j]) * ci + EPS) * rinv[i];
        o[(size_t)i * JJ + j] = __float2half_rn(v);
    }
}

// ---------------------------------------------------------------------------
// Fused GRU + LayerNorm(ff): one block per row. GRU update (torch gate order
// r,z,n) in registers, write slots, then row LN -> lnb16.
// 256 threads x 4 elements.
// ---------------------------------------------------------------------------
__global__ void gru_ln_kernel(const __half* __restrict__ gi,
                              const __half* __restrict__ gh,
                              float* __restrict__ slots,
                              __half* __restrict__ lnb,
                              const float* __restrict__ g,
                              const float* __restrict__ b) {
    const int row = blockIdx.x;
    const int t = threadIdx.x;
    const size_t o3 = (size_t)row * (3 * DD) + t * 4;
    const size_t o1 = (size_t)row * DD + t * 4;

    uint2 uir = *(const uint2*)(gi + o3);
    uint2 uhr = *(const uint2*)(gh + o3);
    uint2 uiz = *(const uint2*)(gi + o3 + DD);
    uint2 uhz = *(const uint2*)(gh + o3 + DD);
    uint2 uin = *(const uint2*)(gi + o3 + 2 * DD);
    uint2 uhn = *(const uint2*)(gh + o3 + 2 * DD);
    float4 hv = *(const float4*)(slots + o1);
    float h[4] = { hv.x, hv.y, hv.z, hv.w };

    float nv[4];
    #pragma unroll
    for (int u = 0; u < 2; u++) {
        float2 ir = __half22float2(((const __half2*)&uir)[u]);
        float2 hr = __half22float2(((const __half2*)&uhr)[u]);
        float2 iz = __half22float2(((const __half2*)&uiz)[u]);
        float2 hz = __half22float2(((const __half2*)&uhz)[u]);
        float2 in_ = __half22float2(((const __half2*)&uin)[u]);
        float2 hn = __half22float2(((const __half2*)&uhn)[u]);
        float r0 = sigm_fast(ir.x + hr.x), r1 = sigm_fast(ir.y + hr.y);
        float z0 = sigm_fast(iz.x + hz.x), z1 = sigm_fast(iz.y + hz.y);
        float n0 = tanh_fast(in_.x + r0 * hn.x);
        float n1 = tanh_fast(in_.y + r1 * hn.y);
        nv[2 * u + 0] = (1.f - z0) * n0 + z0 * h[2 * u + 0];
        nv[2 * u + 1] = (1.f - z1) * n1 + z1 * h[2 * u + 1];
    }

    // write updated slots
    float4 ov = { nv[0], nv[1], nv[2], nv[3] };
    *(float4*)(slots + o1) = ov;

    // LayerNorm over the row
    float s = nv[0] + nv[1] + nv[2] + nv[3];
    float q = nv[0] * nv[0] + nv[1] * nv[1] + nv[2] * nv[2] + nv[3] * nv[3];
    s = warp_sum(s);
    q = warp_sum(q);
    __shared__ float s1[8], s2[8];
    if ((t & 31) == 0) { s1[t >> 5] = s; s2[t >> 5] = q; }
    __syncthreads();
    float S = 0.f, Q = 0.f;
    #pragma unroll
    for (int w = 0; w < 8; w++) { S += s1[w]; Q += s2[w]; }
    const float mean = S * (1.f / DD);
    const float var  = Q * (1.f / DD) - mean * mean;
    const float inv  = rsqrtf(var + LN_EPS);
    float4 gv = ((const float4*)g)[t];
    float4 bv = ((const float4*)b)[t];
    __half2 l01 = __floats2half2_rn((nv[0] - mean) * inv * gv.x + bv.x,
                                    (nv[1] - mean) * inv * gv.y + bv.y);
    __half2 l23 = __floats2half2_rn((nv[2] - mean) * inv * gv.z + bv.z,
                                    (nv[3] - mean) * inv * gv.w + bv.w);
    *(uint2*)(lnb + o1) = make_uint2(*(uint32_t*)&l01, *(uint32_t*)&l23);
}

// ---------------------------------------------------------------------------
// Launch
// ---------------------------------------------------------------------------
static inline void gemm(const __half* A, const __half* B, float* C, __half* C16,
                        int M, int N, int K,
                        const float* bias, const float* resid, float alpha, int relu) {
    dim3 grid(N / 128, M / 128);
    gemm_h_kernel<<<grid, 256, SMEM_DYN>>>(A, B, C, C16, M, N, K, bias, resid,
                                           alpha, relu);
}

static inline void f2h(const float* in, __half* out, int n) {
    f2h_kernel<<<(n / 4 + 255) / 256, 256>>>(in, out, n / 4);
}

extern "C" void kernel_launch(void* const* d_in, const int* in_sizes, int n_in,
                              void* d_out, int out_size) {
    const float* inputs = (const float*)d_in[0];
    const float* texts  = (const float*)d_in[1];
    const float* Wq   = (const float*)d_in[2];  const float* bq   = (const float*)d_in[3];
    const float* Wk   = (const float*)d_in[4];  const float* bk   = (const float*)d_in[5];
    const float* Wv   = (const float*)d_in[6];  const float* bv   = (const float*)d_in[7];
    const float* W_ih = (const float*)d_in[8];  const float* b_ih = (const float*)d_in[9];
    const float* W_hh = (const float*)d_in[10]; const float* b_hh = (const float*)d_in[11];
    const float* W1   = (const float*)d_in[12]; const float* b1   = (const float*)d_in[13];
    const float* W2   = (const float*)d_in[14]; const float* b2   = (const float*)d_in[15];
    const float* gin  = (const float*)d_in[16]; const float* bein = (const float*)d_in[17];
    const float* gsl  = (const float*)d_in[18]; const float* besl = (const float*)d_in[19];
    const float* gff  = (const float*)d_in[20]; const float* beff = (const float*)d_in[21];

    cudaFuncSetAttribute(gemm_h_kernel, cudaFuncAttributeMaxDynamicSharedMemorySize,
                         SMEM_DYN);
    cudaFuncSetAttribute(softmax_fused_kernel,
                         cudaFuncAttributeMaxDynamicSharedMemorySize, SMEM_SOFTMAX);

    float *slots, *attn;
    __half *gi16, *gh16;
    __half *txn16, *k16, *v16, *vT16, *q16, *attn16, *upd16, *hid16, *lnb16, *slots16;
    __half *Wq16, *Wk16, *Wv16, *Wih16, *Whh16, *W116, *W216;
    cudaGetSymbolAddress((void**)&slots,  g_slots);
    cudaGetSymbolAddress((void**)&attn,   g_attn);
    cudaGetSymbolAddress((void**)&gi16,   g_gi16);
    cudaGetSymbolAddress((void**)&gh16,   g_gh16);
    cudaGetSymbolAddress((void**)&txn16,  g_txn16);
    cudaGetSymbolAddress((void**)&k16,    g_k16);
    cudaGetSymbolAddress((void**)&v16,    g_v16);
    cudaGetSymbolAddress((void**)&vT16,   g_vT16);
    cudaGetSymbolAddress((void**)&q16,    g_q16);
    cudaGetSymbolAddress((void**)&attn16, g_attn16);
    cudaGetSymbolAddress((void**)&upd16,  g_upd16);
    cudaGetSymbolAddress((void**)&hid16,  g_hid16);
    cudaGetSymbolAddress((void**)&lnb16,  g_lnb16);
    cudaGetSymbolAddress((void**)&slots16,g_slots16);
    cudaGetSymbolAddress((void**)&Wq16,   g_Wq16);
    cudaGetSymbolAddress((void**)&Wk16,   g_Wk16);
    cudaGetSymbolAddress((void**)&Wv16,   g_Wv16);
    cudaGetSymbolAddress((void**)&Wih16,  g_Wih16);
    cudaGetSymbolAddress((void**)&Whh16,  g_Whh16);
    cudaGetSymbolAddress((void**)&W116,   g_W116);
    cudaGetSymbolAddress((void**)&W216,   g_W216);

    // Weight + input conversions (once per launch; ~40us total)
    f2h(Wq, Wq16, DD * DD);
    f2h(Wk, Wk16, DD * DD);
    f2h(Wv, Wv16, DD * DD);
    f2h(W_ih, Wih16, 3 * DD * DD);
    f2h(W_hh, Whh16, 3 * DD * DD);
    f2h(W1, W116, HH * DD);
    f2h(W2, W216, DD * HH);
    f2h(inputs, slots16, MM * DD);

    // slots = inputs (fp32 master copy)
    cudaMemcpyAsync(slots, inputs, (size_t)MM * DD * sizeof(float),
                    cudaMemcpyDeviceToDevice);

    // texts_n = LN(texts); k/v = texts_n @ W^T + b (fp16); vT = v^T
    ln_kernel<<<JJ, 256>>>(texts, txn16, gin, bein);
    gemm(txn16, Wk16, 0, k16, JJ, DD, DD, bk, 0, 1.f, 0);
    gemm(txn16, Wv16, 0, v16, JJ, DD, DD, bv, 0, 1.f, 0);
    transpose_h_kernel<<<dim3(DD / 32, JJ / 32), dim3(32, 8)>>>(v16, vT16, JJ, DD);

    for (int it = 0; it < 3; it++) {
        // q = LN(slots) @ Wq^T + bq (fp16)
        ln_kernel<<<MM, 256>>>(slots, lnb16, gsl, besl);
        gemm(lnb16, Wq16, 0, q16, MM, DD, DD, bq, 0, 1.f, 0);

        // dots = q @ k^T * SCALE -> fp32
        gemm(q16, k16, attn, 0, MM, JJ, DD, 0, 0, SCALE, 0);

        // fused: softmax over slots axis (+EPS) + renormalize over j -> fp16
        softmax_fused_kernel<<<BB, JJ, SMEM_SOFTMAX>>>(attn, attn16);

        // updates = attn @ v (fp16)
        gemm(attn16, vT16, 0, upd16, MM, DD, JJ, 0, 0, 1.f, 0);

        // GRU gates (fp16 outputs; bias added fp32 in epilogue then rounded)
        gemm(upd16,   Wih16, 0, gi16, MM, 3 * DD, DD, b_ih, 0, 1.f, 0);
        gemm(slots16, Whh16, 0, gh16, MM, 3 * DD, DD, b_hh, 0, 1.f, 0);

        // fused: GRU update + LayerNorm(ff) -> slots, lnb16
        gru_ln_kernel<<<MM, 256>>>(gi16, gh16, slots, lnb16, gff, beff);

        // FF: slots += relu(LN(slots) @ W1^T + b1) @ W2^T + b2
        gemm(lnb16, W116, 0, hid16, MM, HH, DD, b1, 0, 1.f, 1);
        float* outp = (it == 2) ? (float*)d_out : slots;
        gemm(hid16, W216, outp, slots16, MM, DD, HH, b2, slots, 1.f, 0);
    }
}

// round 15
// speedup vs baseline: 7.5778x; 1.1888x over previous
#include <cuda_runtime.h>
#include <cuda_fp16.h>
#include <math.h>
#include <stdint.h>

// Problem constants
#define BB 64
#define NN 128
#define JJ 512
#define DD 1024
#define HH 4096
#define MM (BB * NN)          // 8192 rows
#define SCALE 0.03125f        // 1024^-0.5
#define EPS 1e-8f
#define LN_EPS 1e-5f

// ---------------------------------------------------------------------------
// Scratch (device globals; no allocations allowed)
// ---------------------------------------------------------------------------
__device__ float g_slots[MM * DD];
__device__ float g_attn [MM * JJ];
__device__ float g_dotsb[JJ];

__device__ __align__(16) __half g_gi16  [MM * 3 * DD];
__device__ __align__(16) __half g_gh16  [MM * 3 * DD];
__device__ __align__(16) __half g_txn16 [JJ * DD];
__device__ __align__(16) __half g_k16   [JJ * DD];
__device__ __align__(16) __half g_v16   [JJ * DD];
__device__ __align__(16) __half g_kq16  [JJ * DD];
__device__ __align__(16) __half g_vW16  [JJ * 3 * DD];
__device__ __align__(16) __half g_vWT16 [3 * DD * JJ];
__device__ __align__(16) __half g_attn16[MM * JJ];
__device__ __align__(16) __half g_hid16 [MM * HH];
__device__ __align__(16) __half g_lnb16 [MM * DD];
__device__ __align__(16) __half g_slots16[MM * DD];
__device__ __align__(16) __half g_Wq16  [DD * DD];
__device__ __align__(16) __half g_WqT16 [DD * DD];
__device__ __align__(16) __half g_Wk16  [DD * DD];
__device__ __align__(16) __half g_Wv16  [DD * DD];
__device__ __align__(16) __half g_Wih16 [3 * DD * DD];
__device__ __align__(16) __half g_Whh16 [3 * DD * DD];
__device__ __align__(16) __half g_W116  [HH * DD];
__device__ __align__(16) __half g_W216  [DD * HH];

// ---------------------------------------------------------------------------
// Helpers
// ---------------------------------------------------------------------------
__device__ __forceinline__ float warp_sum(float v) {
    #pragma unroll
    for (int o = 16; o; o >>= 1) v += __shfl_xor_sync(0xFFFFFFFFu, v, o);
    return v;
}

__device__ __forceinline__ uint32_t smem_u32(const void* p) {
    uint32_t a;
    asm("{ .reg .u64 t; cvta.to.shared.u64 t, %1; cvt.u32.u64 %0, t; }"
        : "=r"(a) : "l"(p));
    return a;
}

__device__ __forceinline__ float tanh_fast(float x) {
    float y;
    asm("tanh.approx.f32 %0, %1;" : "=f"(y) : "f"(x));
    return y;
}
__device__ __forceinline__ float sigm_fast(float x) {
    return 1.f / (1.f + __expf(-x));
}

// m16n8k16 fp16 MMA, fp32 accumulate (sm_80+ baseline)
__device__ __forceinline__ void mma_f16(float* c,
                                        uint32_t a0, uint32_t a1, uint32_t a2, uint32_t a3,
                                        uint32_t b0, uint32_t b1) {
    asm volatile(
        "mma.sync.aligned.m16n8k16.row.col.f32.f16.f16.f32 "
        "{%0,%1,%2,%3}, {%4,%5,%6,%7}, {%8,%9}, {%0,%1,%2,%3};"
        : "+f"(c[0]), "+f"(c[1]), "+f"(c[2]), "+f"(c[3])
        : "r"(a0), "r"(a1), "r"(a2), "r"(a3), "r"(b0), "r"(b1));
}

__device__ __forceinline__ void ldsm_x4(uint32_t& r0, uint32_t& r1,
                                        uint32_t& r2, uint32_t& r3, uint32_t addr) {
    asm volatile("ldmatrix.sync.aligned.m8n8.x4.shared.b16 {%0,%1,%2,%3}, [%4];"
                 : "=r"(r0), "=r"(r1), "=r"(r2), "=r"(r3) : "r"(addr));
}

#define CP16(smem, gptr) \
    asm volatile("cp.async.cg.shared.global [%0], [%1], 16;" \
                 :: "r"(smem), "l"(gptr))
#define CP_COMMIT() asm volatile("cp.async.commit_group;")
#define CP_WAIT2()  asm volatile("cp.async.wait_group 2;")
#define CP_WAIT1()  asm volatile("cp.async.wait_group 1;")
#define CP_WAIT0()  asm volatile("cp.async.wait_group 0;")

// ---------------------------------------------------------------------------
// fp32 -> fp16 conversion (n must be a multiple of 4)
// ---------------------------------------------------------------------------
__global__ void f2h_kernel(const float* __restrict__ in, __half* __restrict__ out,
                           int n4) {
    const int i = blockIdx.x * blockDim.x + threadIdx.x;
    if (i < n4) {
        float4 v = ((const float4*)in)[i];
        __half2 h01 = __floats2half2_rn(v.x, v.y);
        __half2 h23 = __floats2half2_rn(v.z, v.w);
        ((uint2*)out)[i] = make_uint2(*(uint32_t*)&h01, *(uint32_t*)&h23);
    }
}

// ---------------------------------------------------------------------------
// dots bias: dotsb[j] = SCALE * sum_d k16[j,d] * bq[d]. Grid JJ x 256 thr.
// ---------------------------------------------------------------------------
__global__ void dotsb_kernel(const __half* __restrict__ k,
                             const float* __restrict__ bq,
                             float* __restrict__ out) {
    const int row = blockIdx.x;
    const int t = threadIdx.x;
    const __half* kr = k + (size_t)row * DD;
    float s = 0.f;
    #pragma unroll
    for (int u = 0; u < 4; u++) {
        const int d = t * 4 + u;
        s += __half2float(kr[d]) * bq[d];
    }
    s = warp_sum(s);
    __shared__ float ws[8];
    if ((t & 31) == 0) ws[t >> 5] = s;
    __syncthreads();
    if (t == 0) {
        float S = 0.f;
        #pragma unroll
        for (int w = 0; w < 8; w++) S += ws[w];
        out[row] = S * SCALE;
    }
}

// ---------------------------------------------------------------------------
// LayerNorm: fp32 in -> fp16 out. One block per row, D=1024, 256 threads.
// ---------------------------------------------------------------------------
__global__ void ln_kernel(const float* __restrict__ x, __half* __restrict__ y,
                          const float* __restrict__ g, const float* __restrict__ b) {
    const int row = blockIdx.x;
    const int t = threadIdx.x;
    const float4* xr = (const float4*)(x + (size_t)row * DD);
    float4 v = xr[t];
    float s = v.x + v.y + v.z + v.w;
    float q = v.x * v.x + v.y * v.y + v.z * v.z + v.w * v.w;
    s = warp_sum(s);
    q = warp_sum(q);
    __shared__ float s1[8], s2[8];
    if ((t & 31) == 0) { s1[t >> 5] = s; s2[t >> 5] = q; }
    __syncthreads();
    float S = 0.f, Q = 0.f;
    #pragma unroll
    for (int w = 0; w < 8; w++) { S += s1[w]; Q += s2[w]; }
    const float mean = S * (1.f / DD);
    const float var  = Q * (1.f / DD) - mean * mean;
    const float inv  = rsqrtf(var + LN_EPS);
    float4 gv = ((const float4*)g)[t];
    float4 bv = ((const float4*)b)[t];
    __half2 o01 = __floats2half2_rn((v.x - mean) * inv * gv.x + bv.x,
                                    (v.y - mean) * inv * gv.y + bv.y);
    __half2 o23 = __floats2half2_rn((v.z - mean) * inv * gv.z + bv.z,
                                    (v.w - mean) * inv * gv.w + bv.w);
    *(uint2*)(y + (size_t)row * DD + t * 4) =
        make_uint2(*(uint32_t*)&o01, *(uint32_t*)&o23);
}

// ---------------------------------------------------------------------------
// Tensor-core FP16 NT GEMM, 3-stage cp.async pipeline (dynamic SMEM).
// C[M,N] = alpha*A[M,K]@B[N,K]^T (+bias)(relu)(+resid); fp32 and/or fp16 out.
// CTA 128x128, BK=32, 256 threads (8 warps, warp tile 64x32).
// ---------------------------------------------------------------------------
#define LDPH 40                       // halves per SMEM row (32 + 8 pad)
#define ROWB (LDPH * 2)               // 80 bytes per row
#define HALFBUF (128 * ROWB)          // 10240 bytes (one operand tile)
#define SBUF (2 * HALFBUF)            // 20480 bytes per stage (A + B)
#define SMEM_DYN (3 * SBUF)           // 61440 bytes

__global__ __launch_bounds__(256, 2)
void gemm_h_kernel(const __half* __restrict__ A, const __half* __restrict__ Bw,
                   float* __restrict__ C, __half* __restrict__ C16,
                   int M, int N, int K,
                   const float* __restrict__ bias, const float* __restrict__ resid,
                   float alpha, int relu) {
    extern __shared__ __align__(16) char smem_raw[];
    const uint32_t sbase = smem_u32(smem_raw);

    const int tid  = threadIdx.x;
    const int warp = tid >> 5;
    const int lane = tid & 31;
    const int gid  = lane >> 2;
    const int tig  = lane & 3;
    const int wm = (warp >> 2) * 64;
    const int wn = (warp & 3) * 32;
    const int bm = blockIdx.y * 128;
    const int bn = blockIdx.x * 128;

    const int sr = tid >> 2;          // staging rows 0..63 (slot 0), +64
    const int sg = tid & 3;           // 16B group in row

    const uint32_t sa0 = sbase + (uint32_t)(sr * ROWB + sg * 16);
    const uint32_t sa1 = sa0 + 64 * ROWB;
    const uint32_t sb0 = sa0 + HALFBUF;
    const uint32_t sb1 = sa1 + HALFBUF;

    const uint32_t a_base0 = sbase +
        (uint32_t)((wm + (lane & 15)) * ROWB + (lane >> 4) * 16);
    const uint32_t b_base0 = sbase + HALFBUF +
        (uint32_t)((wn + ((lane >> 4) << 3) + (lane & 7)) * ROWB +
                   ((lane >> 3) & 1) * 16);

    float acc[4][4][4];
    #pragma unroll
    for (int mf = 0; mf < 4; mf++)
        #pragma unroll
        for (int nf = 0; nf < 4; nf++)
            #pragma unroll
            for (int u = 0; u < 4; u++) acc[mf][nf][u] = 0.f;

    const int nch = K >> 5;

    #define STAGE(c, buf) do {                                            \
        const int _k0 = (c) << 5;                                         \
        const uint32_t _off = (uint32_t)(buf) * SBUF;                     \
        CP16(sa0 + _off, A  + (size_t)(bm + sr) * K + _k0 + sg * 8);      \
        CP16(sa1 + _off, A  + (size_t)(bm + sr + 64) * K + _k0 + sg * 8); \
        CP16(sb0 + _off, Bw + (size_t)(bn + sr) * K + _k0 + sg * 8);      \
        CP16(sb1 + _off, Bw + (size_t)(bn + sr + 64) * K + _k0 + sg * 8); \
        CP_COMMIT();                                                      \
    } while (0)

    STAGE(0, 0);
    if (nch > 1) STAGE(1, 1);

    int buf = 0;
    for (int c = 0; c < nch; c++) {
        const int ahead = nch - 1 - c;
        if (ahead >= 2) STAGE(c + 2, (buf + 2 >= 3) ? buf - 1 : buf + 2);
        if (ahead >= 2)      { CP_WAIT2(); }
        else if (ahead == 1) { CP_WAIT1(); }
        else                 { CP_WAIT0(); }
        __syncthreads();

        const uint32_t aB = a_base0 + (uint32_t)buf * SBUF;
        const uint32_t bB = b_base0 + (uint32_t)buf * SBUF;
        #pragma unroll
        for (int ks = 0; ks < 2; ks++) {
            const uint32_t koff = (uint32_t)(ks * 16 * 2);
            uint32_t b[4][2];
            ldsm_x4(b[0][0], b[0][1], b[1][0], b[1][1], bB + koff);
            ldsm_x4(b[2][0], b[2][1], b[3][0], b[3][1],
                    bB + koff + 16 * ROWB);
            #pragma unroll
            for (int mf = 0; mf < 4; mf++) {
                uint32_t a0, a1, a2, a3;
                ldsm_x4(a0, a1, a2, a3,
                        aB + koff + (uint32_t)(mf * 16 * ROWB));
                #pragma unroll
                for (int nf = 0; nf < 4; nf++)
                    mma_f16(acc[mf][nf], a0, a1, a2, a3, b[nf][0], b[nf][1]);
            }
        }
        __syncthreads();
        buf = (buf + 1 >= 3) ? 0 : buf + 1;
    }
    #undef STAGE

    // Epilogue
    #pragma unroll
    for (int mf = 0; mf < 4; mf++) {
        #pragma unroll
        for (int nf = 0; nf < 4; nf++) {
            const int cc = bn + wn + nf * 8 + 2 * tig;
            float bx = 0.f, by = 0.f;
            if (bias) { bx = bias[cc]; by = bias[cc + 1]; }
            #pragma unroll
            for (int h = 0; h < 2; h++) {
                const int row = bm + wm + mf * 16 + gid + h * 8;
                float v0 = acc[mf][nf][2 * h + 0] * alpha + bx;
                float v1 = acc[mf][nf][2 * h + 1] * alpha + by;
                if (relu) { v0 = fmaxf(v0, 0.f); v1 = fmaxf(v1, 0.f); }
                if (resid) {
                    float2 rr = *(const float2*)(resid + (size_t)row * N + cc);
                    v0 += rr.x; v1 += rr.y;
                }
                if (C) {
                    float2 ov = { v0, v1 };
                    *(float2*)(C + (size_t)row * N + cc) = ov;
                }
                if (C16) {
                    __half2 hv = __floats2half2_rn(v0, v1);
                    *(uint32_t*)(C16 + (size_t)row * N + cc) = *(uint32_t*)&hv;
                }
            }
        }
    }
}

// ---------------------------------------------------------------------------
// fp16 transpose (rows x cols) -> (cols x rows), 32x32 tiles
// ---------------------------------------------------------------------------
__global__ void transpose_h_kernel(const __half* __restrict__ in,
                                   __half* __restrict__ out, int R, int C) {
    __shared__ __half tile[32][34];
    const int c0 = blockIdx.x * 32;
    const int r0 = blockIdx.y * 32;
    for (int dy = threadIdx.y; dy < 32; dy += 8)
        tile[dy][threadIdx.x] = in[(size_t)(r0 + dy) * C + c0 + threadIdx.x];
    __syncthreads();
    for (int dy = threadIdx.y; dy < 32; dy += 8)
        out[(size_t)(c0 + dy) * R + r0 + threadIdx.x] = tile[threadIdx.x][dy];
}

// ---------------------------------------------------------------------------
// Fused softmax: per batch b, softmax over slots axis (i) per column j,
// +EPS, then renormalize over j, write fp16. One CTA per b, 512 threads.
// ---------------------------------------------------------------------------
#define SMEM_SOFTMAX (NN * JJ * 2)

__global__ void softmax_fused_kernel(const float* __restrict__ attn,
                                     __half* __restrict__ out) {
    extern __shared__ __half sh[];            // [NN][JJ] unnormalized exp
    __shared__ float cinv[JJ];
    __shared__ float rinv[NN];
    const int b = blockIdx.x;
    const int j = threadIdx.x;                // 0..511
    const float* base = attn + (size_t)b * NN * JJ;

    float m = -3.0e38f;
    for (int i = 0; i < NN; i++)
        m = fmaxf(m, base[(size_t)i * JJ + j]);

    float s = 0.f;
    for (int i = 0; i < NN; i++) {
        float e = __expf(base[(size_t)i * JJ + j] - m);
        s += e;
        sh[i * JJ + j] = __float2half_rn(e);
    }
    cinv[j] = 1.f / s;
    __syncthreads();

    const int warp = j >> 5, lane = j & 31;
    for (int r = warp * 8; r < warp * 8 + 8; r++) {
        float s2 = 0.f;
        for (int c = lane; c < JJ; c += 32)
            s2 += __half2float(sh[r * JJ + c]) * cinv[c];
        s2 = warp_sum(s2);
        if (lane == 0) rinv[r] = 1.f / (s2 + (float)JJ * EPS);
    }
    __syncthreads();

    __half* o = out + (size_t)b * NN * JJ;
    const float ci = cinv[j];
    for (int i = 0; i < NN; i++) {
        float v = (__half2float(sh[i * JJ + j]) * ci + EPS) * rinv[i];
        o[(size_t)i * JJ + j] = __float2half_rn(v);
    }
}

// ---------------------------------------------------------------------------
// Fused GRU + LayerNorm(ff): one block per row. 256 threads x 4 elements.
// ---------------------------------------------------------------------------
__global__ void gru_ln_kernel(const __half* __restrict__ gi,
                              const __half* __restrict__ gh,
                              float* __restrict__ slots,
                              __half* __restrict__ lnb,
                              const float* __restrict__ g,
                              const float* __restrict__ b) {
    const int row = blockIdx.x;
    const int t = threadIdx.x;
    const size_t o3 = (size_t)row * (3 * DD) + t * 4;
    const size_t o1 = (size_t)row * DD + t * 4;

    uint2 uir = *(const uint2*)(gi + o3);
    uint2 uhr = *(const uint2*)(gh + o3);
    uint2 uiz = *(const uint2*)(gi + o3 + DD);
    uint2 uhz = *(const uint2*)(gh + o3 + DD);
    uint2 uin = *(const uint2*)(gi + o3 + 2 * DD);
    uint2 uhn = *(const uint2*)(gh + o3 + 2 * DD);
    float4 hv = *(const float4*)(slots + o1);
    float h[4] = { hv.x, hv.y, hv.z, hv.w };

    float nv[4];
    #pragma unroll
    for (int u = 0; u < 2; u++) {
        float2 ir = __half22float2(((const __half2*)&uir)[u]);
        float2 hr = __half22float2(((const __half2*)&uhr)[u]);
        float2 iz = __half22float2(((const __half2*)&uiz)[u]);
        float2 hz = __half22float2(((const __half2*)&uhz)[u]);
        float2 in_ = __half22float2(((const __half2*)&uin)[u]);
        float2 hn = __half22float2(((const __half2*)&uhn)[u]);
        float r0 = sigm_fast(ir.x + hr.x), r1 = sigm_fast(ir.y + hr.y);
        float z0 = sigm_fast(iz.x + hz.x), z1 = sigm_fast(iz.y + hz.y);
        float n0 = tanh_fast(in_.x + r0 * hn.x);
        float n1 = tanh_fast(in_.y + r1 * hn.y);
        nv[2 * u + 0] = (1.f - z0) * n0 + z0 * h[2 * u + 0];
        nv[2 * u + 1] = (1.f - z1) * n1 + z1 * h[2 * u + 1];
    }

    float4 ov = { nv[0], nv[1], nv[2], nv[3] };
    *(float4*)(slots + o1) = ov;

    float s = nv[0] + nv[1] + nv[2] + nv[3];
    float q = nv[0] * nv[0] + nv[1] * nv[1] + nv[2] * nv[2] + nv[3] * nv[3];
    s = warp_sum(s);
    q = warp_sum(q);
    __shared__ float s1[8], s2[8];
    if ((t & 31) == 0) { s1[t >> 5] = s; s2[t >> 5] = q; }
    __syncthreads();
    float S = 0.f, Q = 0.f;
    #pragma unroll
    for (int w = 0; w < 8; w++) { S += s1[w]; Q += s2[w]; }
    const float mean = S * (1.f / DD);
    const float var  = Q * (1.f / DD) - mean * mean;
    const float inv  = rsqrtf(var + LN_EPS);
    float4 gv = ((const float4*)g)[t];
    float4 bv = ((const float4*)b)[t];
    __half2 l01 = __floats2half2_rn((nv[0] - mean) * inv * gv.x + bv.x,
                                    (nv[1] - mean) * inv * gv.y + bv.y);
    __half2 l23 = __floats2half2_rn((nv[2] - mean) * inv * gv.z + bv.z,
                                    (nv[3] - mean) * inv * gv.w + bv.w);
    *(uint2*)(lnb + o1) = make_uint2(*(uint32_t*)&l01, *(uint32_t*)&l23);
}

// ---------------------------------------------------------------------------
// Launch
// ---------------------------------------------------------------------------
static inline void gemm(const __half* A, const __half* B, float* C, __half* C16,
                        int M, int N, int K,
                        const float* bias, const float* resid, float alpha, int relu) {
    dim3 grid(N / 128, M / 128);
    gemm_h_kernel<<<grid, 256, SMEM_DYN>>>(A, B, C, C16, M, N, K, bias, resid,
                                           alpha, relu);
}

static inline void f2h(const float* in, __half* out, int n) {
    f2h_kernel<<<(n / 4 + 255) / 256, 256>>>(in, out, n / 4);
}

extern "C" void kernel_launch(void* const* d_in, const int* in_sizes, int n_in,
                              void* d_out, int out_size) {
    const float* inputs = (const float*)d_in[0];
    const float* texts  = (const float*)d_in[1];
    const float* Wq   = (const float*)d_in[2];  const float* bq   = (const float*)d_in[3];
    const float* Wk   = (const float*)d_in[4];  const float* bk   = (const float*)d_in[5];
    const float* Wv   = (const float*)d_in[6];  const float* bv   = (const float*)d_in[7];
    const float* W_ih = (const float*)d_in[8];  const float* b_ih = (const float*)d_in[9];
    const float* W_hh = (const float*)d_in[10]; const float* b_hh = (const float*)d_in[11];
    const float* W1   = (const float*)d_in[12]; const float* b1   = (const float*)d_in[13];
    const float* W2   = (const float*)d_in[14]; const float* b2   = (const float*)d_in[15];
    const float* gin  = (const float*)d_in[16]; const float* bein = (const float*)d_in[17];
    const float* gsl  = (const float*)d_in[18]; const float* besl = (const float*)d_in[19];
    const float* gff  = (const float*)d_in[20]; const float* beff = (const float*)d_in[21];

    cudaFuncSetAttribute(gemm_h_kernel, cudaFuncAttributeMaxDynamicSharedMemorySize,
                         SMEM_DYN);
    cudaFuncSetAttribute(softmax_fused_kernel,
                         cudaFuncAttributeMaxDynamicSharedMemorySize, SMEM_SOFTMAX);

    float *slots, *attn, *dotsb;
    __half *gi16, *gh16;
    __half *txn16, *k16, *v16, *kq16, *vW16, *vWT16, *attn16, *hid16, *lnb16, *slots16;
    __half *Wq16, *WqT16, *Wk16, *Wv16, *Wih16, *Whh16, *W116, *W216;
    cudaGetSymbolAddress((void**)&slots,  g_slots);
    cudaGetSymbolAddress((void**)&attn,   g_attn);
    cudaGetSymbolAddress((void**)&dotsb,  g_dotsb);
    cudaGetSymbolAddress((void**)&gi16,   g_gi16);
    cudaGetSymbolAddress((void**)&gh16,   g_gh16);
    cudaGetSymbolAddress((void**)&txn16,  g_txn16);
    cudaGetSymbolAddress((void**)&k16,    g_k16);
    cudaGetSymbolAddress((void**)&v16,    g_v16);
    cudaGetSymbolAddress((void**)&kq16,   g_kq16);
    cudaGetSymbolAddress((void**)&vW16,   g_vW16);
    cudaGetSymbolAddress((void**)&vWT16,  g_vWT16);
    cudaGetSymbolAddress((void**)&attn16, g_attn16);
    cudaGetSymbolAddress((void**)&hid16,  g_hid16);
    cudaGetSymbolAddress((void**)&lnb16,  g_lnb16);
    cudaGetSymbolAddress((void**)&slots16,g_slots16);
    cudaGetSymbolAddress((void**)&Wq16,   g_Wq16);
    cudaGetSymbolAddress((void**)&WqT16,  g_WqT16);
    cudaGetSymbolAddress((void**)&Wk16,   g_Wk16);
    cudaGetSymbolAddress((void**)&Wv16,   g_Wv16);
    cudaGetSymbolAddress((void**)&Wih16,  g_Wih16);
    cudaGetSymbolAddress((void**)&Whh16,  g_Whh16);
    cudaGetSymbolAddress((void**)&W116,   g_W116);
    cudaGetSymbolAddress((void**)&W216,   g_W216);

    // Weight + input conversions (once per launch)
    f2h(Wq, Wq16, DD * DD);
    f2h(Wk, Wk16, DD * DD);
    f2h(Wv, Wv16, DD * DD);
    f2h(W_ih, Wih16, 3 * DD * DD);
    f2h(W_hh, Whh16, 3 * DD * DD);
    f2h(W1, W116, HH * DD);
    f2h(W2, W216, DD * HH);
    f2h(inputs, slots16, MM * DD);

    // slots = inputs (fp32 master copy)
    cudaMemcpyAsync(slots, inputs, (size_t)MM * DD * sizeof(float),
                    cudaMemcpyDeviceToDevice);

    // Prologue: texts_n = LN(texts); k/v; folded operands.
    ln_kernel<<<JJ, 256>>>(texts, txn16, gin, bein);
    gemm(txn16, Wk16, 0, k16, JJ, DD, DD, bk, 0, 1.f, 0);
    gemm(txn16, Wv16, 0, v16, JJ, DD, DD, bv, 0, 1.f, 0);
    // kq = k @ Wq  (via WqT as NT B operand)
    transpose_h_kernel<<<dim3(DD / 32, DD / 32), dim3(32, 8)>>>(Wq16, WqT16, DD, DD);
    gemm(k16, WqT16, 0, kq16, JJ, DD, DD, 0, 0, 1.f, 0);
    // dotsb[j] = SCALE * <k[j,:], bq>
    dotsb_kernel<<<JJ, 256>>>(k16, bq, dotsb);
    // vW = v @ W_ih^T  [J, 3D], then vWT [3D, J]
    gemm(v16, Wih16, 0, vW16, JJ, 3 * DD, DD, 0, 0, 1.f, 0);
    transpose_h_kernel<<<dim3(3 * DD / 32, JJ / 32), dim3(32, 8)>>>(vW16, vWT16,
                                                                    JJ, 3 * DD);

    for (int it = 0; it < 3; it++) {
        // lnb = LN(slots)
        ln_kernel<<<MM, 256>>>(slots, lnb16, gsl, besl);

        // dots = SCALE*(lnb @ kq^T) + dotsb  -> fp32  (q GEMM folded away)
        gemm(lnb16, kq16, attn, 0, MM, JJ, DD, dotsb, 0, SCALE, 0);

        // fused softmax over slots axis (+EPS) + renorm over j -> fp16
        softmax_fused_kernel<<<BB, JJ, SMEM_SOFTMAX>>>(attn, attn16);

        // gi = attn @ vW + b_ih  (updates GEMM folded away; K=J=512)
        gemm(attn16, vWT16, 0, gi16, MM, 3 * DD, JJ, b_ih, 0, 1.f, 0);
        // gh = slots @ W_hh^T + b_hh
        gemm(slots16, Whh16, 0, gh16, MM, 3 * DD, DD, b_hh, 0, 1.f, 0);

        // fused GRU update + LayerNorm(ff) -> slots, lnb16
        gru_ln_kernel<<<MM, 256>>>(gi16, gh16, slots, lnb16, gff, beff);

        // FF: slots += relu(LN(slots) @ W1^T + b1) @ W2^T + b2
        gemm(lnb16, W116, 0, hid16, MM, HH, DD, b1, 0, 1.f, 1);
        float* outp = (it == 2) ? (float*)d_out : slots;
        gemm(hid16, W216, outp, slots16, MM, DD, HH, b2, slots, 1.f, 0);
    }
}